// round 1
// baseline (speedup 1.0000x reference)
#include <cuda_runtime.h>

#define NN   50000
#define PP   4
#define EE   500000
#define IND  128
#define HH   8
#define FF   32
#define HFF  256
#define HSS  128
#define BB   128
#define OUTC 2

// ---------------- persistent device scratch (no allocations allowed) ----------------
__device__ float g_hp[PP * NN * HFF];     // projected features per metapath  (204.8 MB)
__device__ float g_z[PP * NN * HFF];      // GAT outputs per metapath         (204.8 MB)
__device__ float g_el[PP * NN * HH];
__device__ float g_er[PP * NN * HH];
__device__ int   g_deg[PP * NN];
__device__ int   g_off[PP * (NN + 1)];
__device__ int   g_cur[PP * NN];
__device__ int   g_csr[PP * EE];
__device__ float g_wsum[PP];
__device__ float g_beta[PP];
__device__ float g_pooled[BB * HFF];
__device__ int   g_cnt[BB];

__device__ __forceinline__ float eluf(float x) {
    return x > 0.f ? x : (__expf(x) - 1.f);
}

// ---------------- init ----------------
__global__ void zero_kernel() {
    int i = blockIdx.x * blockDim.x + threadIdx.x;
    if (i < PP * NN)  g_deg[i] = 0;
    if (i < BB * HFF) g_pooled[i] = 0.f;
    if (i < BB)       g_cnt[i] = 0;
    if (i < PP)       g_wsum[i] = 0.f;
}

// ---------------- CSR build ----------------
__global__ void deg_kernel(const int* __restrict__ dst) {
    int i = blockIdx.x * blockDim.x + threadIdx.x;
    if (i >= PP * EE) return;
    int p = i / EE;
    atomicAdd(&g_deg[p * NN + dst[i]], 1);
}

__global__ void scan_kernel() {
    int p = blockIdx.x;
    __shared__ int wsums[32];
    __shared__ int carry;
    int tid = threadIdx.x, lane = tid & 31, wid = tid >> 5;
    if (tid == 0) { carry = 0; g_off[p * (NN + 1)] = 0; }
    __syncthreads();
    for (int base = 0; base < NN; base += 1024) {
        int i = base + tid;
        int v = (i < NN) ? g_deg[p * NN + i] : 0;
        int x = v;
        #pragma unroll
        for (int d = 1; d < 32; d <<= 1) {
            int t2 = __shfl_up_sync(0xffffffffu, x, d);
            if (lane >= d) x += t2;
        }
        if (lane == 31) wsums[wid] = x;
        __syncthreads();
        if (wid == 0) {
            int y = wsums[lane];
            #pragma unroll
            for (int d = 1; d < 32; d <<= 1) {
                int t2 = __shfl_up_sync(0xffffffffu, y, d);
                if (lane >= d) y += t2;
            }
            wsums[lane] = y;
        }
        __syncthreads();
        int incl = x + (wid ? wsums[wid - 1] : 0) + carry;
        if (i < NN) {
            g_off[p * (NN + 1) + i + 1] = incl;
            g_cur[p * NN + i] = incl - v;
        }
        __syncthreads();
        if (tid == 0) carry += wsums[31];
        __syncthreads();
    }
}

__global__ void fill_kernel(const int* __restrict__ src, const int* __restrict__ dst) {
    int i = blockIdx.x * blockDim.x + threadIdx.x;
    if (i >= PP * EE) return;
    int p = i / EE;
    int d = dst[i];
    int slot = atomicAdd(&g_cur[p * NN + d], 1);
    g_csr[p * EE + slot] = src[i];
}

// ---------------- projection GEMM: hp[p] = h @ Wg[p]  (64x64x16 tile, 4x4 micro) ----------------
__global__ __launch_bounds__(256) void gemm_proj(const float* __restrict__ A,
                                                 const float* __restrict__ Wg) {
    int p = blockIdx.z;
    const float* B = Wg + (size_t)p * IND * HFF;
    float* C = g_hp + (size_t)p * NN * HFF;
    __shared__ float As[16][64];
    __shared__ float Bs[16][64];
    int tid = threadIdx.x;
    int m0 = blockIdx.x * 64, n0 = blockIdx.y * 64;
    int arow = tid >> 2, ak = (tid & 3) << 2;
    int bk = tid >> 4, bcol = (tid & 15) << 2;
    int ty = tid >> 4, tx = tid & 15;
    float acc[4][4] = {};
    int arow_g = m0 + arow;
    if (arow_g >= NN) arow_g = NN - 1;
    for (int k0 = 0; k0 < IND; k0 += 16) {
        float4 av = *(const float4*)(A + (size_t)arow_g * IND + k0 + ak);
        As[ak + 0][arow] = av.x; As[ak + 1][arow] = av.y;
        As[ak + 2][arow] = av.z; As[ak + 3][arow] = av.w;
        float4 bv = *(const float4*)(B + (size_t)(k0 + bk) * HFF + n0 + bcol);
        *(float4*)&Bs[bk][bcol] = bv;
        __syncthreads();
        #pragma unroll
        for (int kk = 0; kk < 16; kk++) {
            float4 a4 = *(const float4*)&As[kk][ty << 2];
            float4 b4 = *(const float4*)&Bs[kk][tx << 2];
            acc[0][0] += a4.x * b4.x; acc[0][1] += a4.x * b4.y; acc[0][2] += a4.x * b4.z; acc[0][3] += a4.x * b4.w;
            acc[1][0] += a4.y * b4.x; acc[1][1] += a4.y * b4.y; acc[1][2] += a4.y * b4.z; acc[1][3] += a4.y * b4.w;
            acc[2][0] += a4.z * b4.x; acc[2][1] += a4.z * b4.y; acc[2][2] += a4.z * b4.z; acc[2][3] += a4.z * b4.w;
            acc[3][0] += a4.w * b4.x; acc[3][1] += a4.w * b4.y; acc[3][2] += a4.w * b4.z; acc[3][3] += a4.w * b4.w;
        }
        __syncthreads();
    }
    #pragma unroll
    for (int i = 0; i < 4; i++) {
        int row = m0 + (ty << 2) + i;
        if (row < NN) {
            float4 o;
            o.x = acc[i][0]; o.y = acc[i][1]; o.z = acc[i][2]; o.w = acc[i][3];
            *(float4*)(C + (size_t)row * HFF + n0 + (tx << 2)) = o;
        }
    }
}

// ---------------- el/er attention terms ----------------
__global__ void eler_kernel(const float* __restrict__ al, const float* __restrict__ ar) {
    int idx = blockIdx.x * blockDim.x + threadIdx.x;
    if (idx >= PP * NN * HH) return;
    int h = idx & 7;
    int pn = idx >> 3;            // p*NN + n
    int p = pn / NN;
    const float* hpr = g_hp + (size_t)pn * HFF + h * FF;
    const float* alr = al + p * HFF + h * FF;
    const float* arr = ar + p * HFF + h * FF;
    float e1 = 0.f, e2 = 0.f;
    #pragma unroll
    for (int f = 0; f < FF; f++) {
        float v = hpr[f];
        e1 += v * alr[f];
        e2 += v * arr[f];
    }
    g_el[idx] = e1;
    g_er[idx] = e2;
}

// ---------------- GAT edge softmax + aggregation: one warp per dst node ----------------
__global__ __launch_bounds__(256) void attn_kernel(const float* __restrict__ bias) {
    int lane = threadIdx.x & 31;
    int v = blockIdx.x * 8 + (threadIdx.x >> 5);
    if (v >= NN) return;
    int p = blockIdx.y;
    int beg = g_off[p * (NN + 1) + v];
    int end = g_off[p * (NN + 1) + v + 1];
    const float* __restrict__ elp = g_el + (size_t)p * NN * HH;
    const float* __restrict__ hpp = g_hp + (size_t)p * NN * HFF;
    const int*   __restrict__ csr = g_csr + (size_t)p * EE;
    float er_l = 0.f;
    if (lane < HH) er_l = g_er[(size_t)p * NN * HH + (size_t)v * HH + lane];
    // pass 1: per-head max (lanes 0..7 own heads)
    float m = -1e30f;
    for (int i = beg; i < end; i++) {
        int s = csr[i];
        if (lane < HH) {
            float e = elp[(size_t)s * HH + lane] + er_l;
            e = e > 0.f ? e : 0.2f * e;
            m = fmaxf(m, e);
        }
    }
    // pass 2: unnormalized accumulate; lane covers cols 4*lane..+3 (head lane/8)
    // and 128+4*lane..+3 (head 4+lane/8)
    int h0 = lane >> 3, h1 = 4 + (lane >> 3);
    float den = 0.f;
    float4 acc0 = {0, 0, 0, 0}, acc1 = {0, 0, 0, 0};
    for (int i = beg; i < end; i++) {
        int s = csr[i];
        float a = 0.f;
        if (lane < HH) {
            float e = elp[(size_t)s * HH + lane] + er_l;
            e = e > 0.f ? e : 0.2f * e;
            a = __expf(e - m);
            den += a;
        }
        float a0 = __shfl_sync(0xffffffffu, a, h0);
        float a1 = __shfl_sync(0xffffffffu, a, h1);
        const float4* r = (const float4*)(hpp + (size_t)s * HFF);
        float4 x0 = r[lane];
        float4 x1 = r[32 + lane];
        acc0.x += a0 * x0.x; acc0.y += a0 * x0.y; acc0.z += a0 * x0.z; acc0.w += a0 * x0.w;
        acc1.x += a1 * x1.x; acc1.y += a1 * x1.y; acc1.z += a1 * x1.z; acc1.w += a1 * x1.w;
    }
    float d0 = __shfl_sync(0xffffffffu, den, h0);
    float d1 = __shfl_sync(0xffffffffu, den, h1);
    float i0 = (end > beg) ? 1.f / d0 : 0.f;
    float i1 = (end > beg) ? 1.f / d1 : 0.f;
    const float* bp = bias + p * HFF;
    float4 b0 = *(const float4*)(bp + (lane << 2));
    float4 b1v = *(const float4*)(bp + 128 + (lane << 2));
    float4 o0, o1;
    o0.x = eluf(acc0.x * i0 + b0.x);  o0.y = eluf(acc0.y * i0 + b0.y);
    o0.z = eluf(acc0.z * i0 + b0.z);  o0.w = eluf(acc0.w * i0 + b0.w);
    o1.x = eluf(acc1.x * i1 + b1v.x); o1.y = eluf(acc1.y * i1 + b1v.y);
    o1.z = eluf(acc1.z * i1 + b1v.z); o1.w = eluf(acc1.w * i1 + b1v.w);
    float4* zr = (float4*)(g_z + ((size_t)p * NN + v) * HFF);
    zr[lane] = o0;
    zr[32 + lane] = o1;
}

// ---------------- semantic attention GEMM with fused tanh·W2 + per-p sum ----------------
__global__ __launch_bounds__(256) void gemm_sem(const float* __restrict__ W1,
                                                const float* __restrict__ b1,
                                                const float* __restrict__ W2) {
    __shared__ float As[16][64];
    __shared__ float Bs[16][64];
    __shared__ float sred[64][17];
    __shared__ float spsum[PP];
    int tid = threadIdx.x;
    if (tid < PP) spsum[tid] = 0.f;
    int m0 = blockIdx.x * 64, n0 = blockIdx.y * 64;
    int arow = tid >> 2, ak = (tid & 3) << 2;
    int bk = tid >> 4, bcol = (tid & 15) << 2;
    int ty = tid >> 4, tx = tid & 15;
    float acc[4][4] = {};
    const float* A = g_z;   // [P*NN][HFF] contiguous
    for (int k0 = 0; k0 < HFF; k0 += 16) {
        float4 av = *(const float4*)(A + (size_t)(m0 + arow) * HFF + k0 + ak);
        As[ak + 0][arow] = av.x; As[ak + 1][arow] = av.y;
        As[ak + 2][arow] = av.z; As[ak + 3][arow] = av.w;
        float4 bv = *(const float4*)(W1 + (size_t)(k0 + bk) * HSS + n0 + bcol);
        *(float4*)&Bs[bk][bcol] = bv;
        __syncthreads();
        #pragma unroll
        for (int kk = 0; kk < 16; kk++) {
            float4 a4 = *(const float4*)&As[kk][ty << 2];
            float4 b4 = *(const float4*)&Bs[kk][tx << 2];
            acc[0][0] += a4.x * b4.x; acc[0][1] += a4.x * b4.y; acc[0][2] += a4.x * b4.z; acc[0][3] += a4.x * b4.w;
            acc[1][0] += a4.y * b4.x; acc[1][1] += a4.y * b4.y; acc[1][2] += a4.y * b4.z; acc[1][3] += a4.y * b4.w;
            acc[2][0] += a4.z * b4.x; acc[2][1] += a4.z * b4.y; acc[2][2] += a4.z * b4.z; acc[2][3] += a4.z * b4.w;
            acc[3][0] += a4.w * b4.x; acc[3][1] += a4.w * b4.y; acc[3][2] += a4.w * b4.z; acc[3][3] += a4.w * b4.w;
        }
        __syncthreads();
    }
    int c0 = n0 + (tx << 2);
    float4 bb = *(const float4*)(b1 + c0);
    float4 ww = *(const float4*)(W2 + c0);
    #pragma unroll
    for (int i = 0; i < 4; i++) {
        float s = tanhf(acc[i][0] + bb.x) * ww.x + tanhf(acc[i][1] + bb.y) * ww.y +
                  tanhf(acc[i][2] + bb.z) * ww.z + tanhf(acc[i][3] + bb.w) * ww.w;
        sred[(ty << 2) + i][tx] = s;
    }
    __syncthreads();
    if (tid < 64) {
        float s = 0.f;
        #pragma unroll
        for (int x = 0; x < 16; x++) s += sred[tid][x];
        int row = m0 + tid;
        atomicAdd(&spsum[row / NN], s);
    }
    __syncthreads();
    if (tid < PP) atomicAdd(&g_wsum[tid], spsum[tid]);
}

// ---------------- beta = softmax over metapaths of mean semantic score ----------------
__global__ void beta_kernel() {
    if (threadIdx.x == 0 && blockIdx.x == 0) {
        float w[PP], m = -1e30f, s = 0.f;
        #pragma unroll
        for (int p = 0; p < PP; p++) { w[p] = g_wsum[p] / (float)NN; m = fmaxf(m, w[p]); }
        #pragma unroll
        for (int p = 0; p < PP; p++) { w[p] = __expf(w[p] - m); s += w[p]; }
        #pragma unroll
        for (int p = 0; p < PP; p++) g_beta[p] = w[p] / s;
    }
}

// ---------------- fused embedding + per-graph pooling ----------------
__global__ __launch_bounds__(256) void fuse_pool(const int* __restrict__ gids) {
    int n = blockIdx.x * 4 + (threadIdx.x >> 6);
    int t = threadIdx.x & 63;
    if (n >= NN) return;
    int g = gids[n];
    float bb0 = g_beta[0], bb1 = g_beta[1], bb2 = g_beta[2], bb3 = g_beta[3];
    float4 v0 = ((const float4*)(g_z + ((size_t)0 * NN + n) * HFF))[t];
    float4 v1 = ((const float4*)(g_z + ((size_t)1 * NN + n) * HFF))[t];
    float4 v2 = ((const float4*)(g_z + ((size_t)2 * NN + n) * HFF))[t];
    float4 v3 = ((const float4*)(g_z + ((size_t)3 * NN + n) * HFF))[t];
    float4 f;
    f.x = bb0 * v0.x + bb1 * v1.x + bb2 * v2.x + bb3 * v3.x;
    f.y = bb0 * v0.y + bb1 * v1.y + bb2 * v2.y + bb3 * v3.y;
    f.z = bb0 * v0.z + bb1 * v1.z + bb2 * v2.z + bb3 * v3.z;
    f.w = bb0 * v0.w + bb1 * v1.w + bb2 * v2.w + bb3 * v3.w;
    float* dp = g_pooled + g * HFF + (t << 2);
    atomicAdd(dp + 0, f.x);
    atomicAdd(dp + 1, f.y);
    atomicAdd(dp + 2, f.z);
    atomicAdd(dp + 3, f.w);
    if (t == 0) atomicAdd(&g_cnt[g], 1);
}

// ---------------- pooled normalize + classifier ----------------
__global__ __launch_bounds__(256) void final_kernel(const float* __restrict__ clsW,
                                                    const float* __restrict__ clsb,
                                                    float* __restrict__ out) {
    int g = blockIdx.x;
    int t = threadIdx.x;
    float cnt = (float)g_cnt[g];
    float inv = 1.f / fmaxf(cnt, 1.f);
    float pv = g_pooled[g * HFF + t] * inv;
    out[BB * OUTC + g * HFF + t] = pv;                 // pooled block
    __shared__ float s0[256], s1[256];
    s0[t] = pv * clsW[t * OUTC + 0];
    s1[t] = pv * clsW[t * OUTC + 1];
    __syncthreads();
    for (int d = 128; d > 0; d >>= 1) {
        if (t < d) { s0[t] += s0[t + d]; s1[t] += s1[t + d]; }
        __syncthreads();
    }
    if (t == 0) {
        out[g * OUTC + 0] = s0[0] + clsb[0];
        out[g * OUTC + 1] = s1[0] + clsb[1];
    }
}

// ---------------- launch ----------------
extern "C" void kernel_launch(void* const* d_in, const int* in_sizes, int n_in,
                              void* d_out, int out_size) {
    const float* h    = (const float*)d_in[0];
    const float* Wg   = (const float*)d_in[1];
    const float* al   = (const float*)d_in[2];
    const float* ar   = (const float*)d_in[3];
    const float* gb   = (const float*)d_in[4];
    const float* sW1  = (const float*)d_in[5];
    const float* sb1  = (const float*)d_in[6];
    const float* sW2  = (const float*)d_in[7];
    const float* cW   = (const float*)d_in[8];
    const float* cb   = (const float*)d_in[9];
    const int*   src  = (const int*)d_in[10];
    const int*   dst  = (const int*)d_in[11];
    const int*   gid  = (const int*)d_in[12];
    float* out = (float*)d_out;

    zero_kernel<<<(PP * NN + 255) / 256, 256>>>();
    deg_kernel<<<(PP * EE + 255) / 256, 256>>>(dst);
    scan_kernel<<<PP, 1024>>>();
    fill_kernel<<<(PP * EE + 255) / 256, 256>>>(src, dst);

    dim3 gp((NN + 63) / 64, HFF / 64, PP);
    gemm_proj<<<gp, 256>>>(h, Wg);

    eler_kernel<<<(PP * NN * HH + 255) / 256, 256>>>(al, ar);

    dim3 ga((NN + 7) / 8, PP);
    attn_kernel<<<ga, 256>>>(gb);

    dim3 gs((PP * NN) / 64, HSS / 64);
    gemm_sem<<<gs, 256>>>(sW1, sb1, sW2);

    beta_kernel<<<1, 32>>>();
    fuse_pool<<<(NN + 3) / 4, 256>>>(gid);
    final_kernel<<<BB, 256>>>(cW, cb, out);
}

// round 2
// speedup vs baseline: 1.3747x; 1.3747x over previous
#include <cuda_runtime.h>
#include <cstdint>

#define NN   50000
#define PP   4
#define EE   500000
#define IND  128
#define HH   8
#define FF   32
#define HFF  256
#define HSS  128
#define BB   128
#define OUTC 2

// ---------------- persistent device scratch ----------------
__device__ float g_hp[PP * NN * HFF];
__device__ float g_z[PP * NN * HFF];
__device__ float g_el[PP * NN * HH];
__device__ float g_er[PP * NN * HH];
__device__ int   g_deg[PP * NN];
__device__ int   g_off[PP * (NN + 1)];
__device__ int   g_cur[PP * NN];
__device__ int   g_csr[PP * EE];
__device__ float g_wsum[PP];
__device__ float g_beta[PP];
__device__ float g_pooled[BB * HFF];
__device__ int   g_cnt[BB];

__device__ __forceinline__ float eluf(float x) {
    return x > 0.f ? x : (__expf(x) - 1.f);
}

__device__ __forceinline__ uint32_t f2tf32(float x) {
    uint32_t y;
    asm("cvt.rna.tf32.f32 %0, %1;" : "=r"(y) : "f"(x));
    return y;
}

__device__ __forceinline__ void mma_tf32(float* c, const uint32_t* a, const uint32_t* b) {
    asm volatile(
        "mma.sync.aligned.m16n8k8.row.col.f32.tf32.tf32.f32 "
        "{%0,%1,%2,%3},{%4,%5,%6,%7},{%8,%9},{%0,%1,%2,%3};"
        : "+f"(c[0]), "+f"(c[1]), "+f"(c[2]), "+f"(c[3])
        : "r"(a[0]), "r"(a[1]), "r"(a[2]), "r"(a[3]), "r"(b[0]), "r"(b[1]));
}

// ---------------- init ----------------
__global__ void zero_kernel() {
    int i = blockIdx.x * blockDim.x + threadIdx.x;
    if (i < PP * NN)  g_deg[i] = 0;
    if (i < BB * HFF) g_pooled[i] = 0.f;
    if (i < BB)       g_cnt[i] = 0;
    if (i < PP)       g_wsum[i] = 0.f;
}

// ---------------- CSR build ----------------
__global__ void deg_kernel(const int* __restrict__ dst) {
    int i = blockIdx.x * blockDim.x + threadIdx.x;
    if (i >= PP * EE) return;
    int p = i / EE;
    atomicAdd(&g_deg[p * NN + dst[i]], 1);
}

__global__ void scan_kernel() {
    int p = blockIdx.x;
    __shared__ int wsums[32];
    __shared__ int carry;
    int tid = threadIdx.x, lane = tid & 31, wid = tid >> 5;
    if (tid == 0) { carry = 0; g_off[p * (NN + 1)] = 0; }
    __syncthreads();
    for (int base = 0; base < NN; base += 1024) {
        int i = base + tid;
        int v = (i < NN) ? g_deg[p * NN + i] : 0;
        int x = v;
        #pragma unroll
        for (int d = 1; d < 32; d <<= 1) {
            int t2 = __shfl_up_sync(0xffffffffu, x, d);
            if (lane >= d) x += t2;
        }
        if (lane == 31) wsums[wid] = x;
        __syncthreads();
        if (wid == 0) {
            int y = wsums[lane];
            #pragma unroll
            for (int d = 1; d < 32; d <<= 1) {
                int t2 = __shfl_up_sync(0xffffffffu, y, d);
                if (lane >= d) y += t2;
            }
            wsums[lane] = y;
        }
        __syncthreads();
        int incl = x + (wid ? wsums[wid - 1] : 0) + carry;
        if (i < NN) {
            g_off[p * (NN + 1) + i + 1] = incl;
            g_cur[p * NN + i] = incl - v;
        }
        __syncthreads();
        if (tid == 0) carry += wsums[31];
        __syncthreads();
    }
}

__global__ void fill_kernel(const int* __restrict__ src, const int* __restrict__ dst) {
    int i = blockIdx.x * blockDim.x + threadIdx.x;
    if (i >= PP * EE) return;
    int p = i / EE;
    int d = dst[i];
    int slot = atomicAdd(&g_cur[p * NN + d], 1);
    g_csr[p * EE + slot] = src[i];
}

// ---------------- projection GEMM (tf32 tensor core): hp[p] = h @ Wg[p] ----------------
// BM=128 BN=64 BK=16, 8 warps (4x2), warp tile 32x32 via m16n8k8
__global__ __launch_bounds__(256) void gemm_proj_tc(const float* __restrict__ A,
                                                    const float* __restrict__ Wg) {
    int p = blockIdx.z;
    const float* B = Wg + (size_t)p * IND * HFF;
    float* C = g_hp + (size_t)p * NN * HFF;

    __shared__ uint32_t As[16][136];  // [k][m], bank-conflict-free frag loads
    __shared__ uint32_t Bs[16][72];   // [k][n]

    int tid = threadIdx.x;
    int warp = tid >> 5, lane = tid & 31;
    int group = lane >> 2, tid4 = lane & 3;
    int warp_m = (warp >> 1) * 32, warp_n = (warp & 1) * 32;
    int m0 = blockIdx.x * 128, n0 = blockIdx.y * 64;

    // A load mapping: rows mA, mA+64; cols kA..kA+3
    int mA = tid >> 2, kA = (tid & 3) << 2;
    // B load mapping
    int kB = tid >> 4, nB = (tid & 15) << 2;

    float acc[2][4][4] = {};

    int rowA0 = m0 + mA;       if (rowA0 >= NN) rowA0 = NN - 1;
    int rowA1 = m0 + mA + 64;  if (rowA1 >= NN) rowA1 = NN - 1;

    for (int k0 = 0; k0 < IND; k0 += 16) {
        float4 a0 = *(const float4*)(A + (size_t)rowA0 * IND + k0 + kA);
        float4 a1 = *(const float4*)(A + (size_t)rowA1 * IND + k0 + kA);
        float4 bv = *(const float4*)(B + (size_t)(k0 + kB) * HFF + n0 + nB);
        __syncthreads();
        As[kA + 0][mA] = f2tf32(a0.x); As[kA + 1][mA] = f2tf32(a0.y);
        As[kA + 2][mA] = f2tf32(a0.z); As[kA + 3][mA] = f2tf32(a0.w);
        As[kA + 0][mA + 64] = f2tf32(a1.x); As[kA + 1][mA + 64] = f2tf32(a1.y);
        As[kA + 2][mA + 64] = f2tf32(a1.z); As[kA + 3][mA + 64] = f2tf32(a1.w);
        Bs[kB][nB + 0] = f2tf32(bv.x); Bs[kB][nB + 1] = f2tf32(bv.y);
        Bs[kB][nB + 2] = f2tf32(bv.z); Bs[kB][nB + 3] = f2tf32(bv.w);
        __syncthreads();
        #pragma unroll
        for (int kk = 0; kk < 16; kk += 8) {
            uint32_t af[2][4], bf[4][2];
            #pragma unroll
            for (int mi = 0; mi < 2; mi++) {
                int r0 = warp_m + mi * 16 + group;
                af[mi][0] = As[kk + tid4][r0];
                af[mi][1] = As[kk + tid4][r0 + 8];
                af[mi][2] = As[kk + tid4 + 4][r0];
                af[mi][3] = As[kk + tid4 + 4][r0 + 8];
            }
            #pragma unroll
            for (int ni = 0; ni < 4; ni++) {
                int cc = warp_n + ni * 8 + group;
                bf[ni][0] = Bs[kk + tid4][cc];
                bf[ni][1] = Bs[kk + tid4 + 4][cc];
            }
            #pragma unroll
            for (int mi = 0; mi < 2; mi++)
                #pragma unroll
                for (int ni = 0; ni < 4; ni++)
                    mma_tf32(acc[mi][ni], af[mi], bf[ni]);
        }
    }

    #pragma unroll
    for (int mi = 0; mi < 2; mi++) {
        int r0 = m0 + warp_m + mi * 16 + group;
        #pragma unroll
        for (int ni = 0; ni < 4; ni++) {
            int col = n0 + warp_n + ni * 8 + (tid4 << 1);
            if (r0 < NN) {
                float2 o = {acc[mi][ni][0], acc[mi][ni][1]};
                *(float2*)(C + (size_t)r0 * HFF + col) = o;
            }
            if (r0 + 8 < NN) {
                float2 o = {acc[mi][ni][2], acc[mi][ni][3]};
                *(float2*)(C + (size_t)(r0 + 8) * HFF + col) = o;
            }
        }
    }
}

// ---------------- el/er attention terms ----------------
__global__ void eler_kernel(const float* __restrict__ al, const float* __restrict__ ar) {
    int idx = blockIdx.x * blockDim.x + threadIdx.x;
    if (idx >= PP * NN * HH) return;
    int h = idx & 7;
    int pn = idx >> 3;
    int p = pn / NN;
    const float* hpr = g_hp + (size_t)pn * HFF + h * FF;
    const float* alr = al + p * HFF + h * FF;
    const float* arr = ar + p * HFF + h * FF;
    float e1 = 0.f, e2 = 0.f;
    #pragma unroll
    for (int f = 0; f < FF; f++) {
        float v = hpr[f];
        e1 += v * alr[f];
        e2 += v * arr[f];
    }
    g_el[idx] = e1;
    g_er[idx] = e2;
}

// ---------------- GAT edge softmax + aggregation ----------------
__global__ __launch_bounds__(256) void attn_kernel(const float* __restrict__ bias) {
    int lane = threadIdx.x & 31;
    int v = blockIdx.x * 8 + (threadIdx.x >> 5);
    if (v >= NN) return;
    int p = blockIdx.y;
    int beg = g_off[p * (NN + 1) + v];
    int end = g_off[p * (NN + 1) + v + 1];
    const float* __restrict__ elp = g_el + (size_t)p * NN * HH;
    const float* __restrict__ hpp = g_hp + (size_t)p * NN * HFF;
    const int*   __restrict__ csr = g_csr + (size_t)p * EE;
    float er_l = 0.f;
    if (lane < HH) er_l = g_er[(size_t)p * NN * HH + (size_t)v * HH + lane];
    float m = -1e30f;
    for (int i = beg; i < end; i++) {
        int s = csr[i];
        if (lane < HH) {
            float e = elp[(size_t)s * HH + lane] + er_l;
            e = e > 0.f ? e : 0.2f * e;
            m = fmaxf(m, e);
        }
    }
    int h0 = lane >> 3, h1 = 4 + (lane >> 3);
    float den = 0.f;
    float4 acc0 = {0, 0, 0, 0}, acc1 = {0, 0, 0, 0};
    for (int i = beg; i < end; i++) {
        int s = csr[i];
        float a = 0.f;
        if (lane < HH) {
            float e = elp[(size_t)s * HH + lane] + er_l;
            e = e > 0.f ? e : 0.2f * e;
            a = __expf(e - m);
            den += a;
        }
        float a0 = __shfl_sync(0xffffffffu, a, h0);
        float a1 = __shfl_sync(0xffffffffu, a, h1);
        const float4* r = (const float4*)(hpp + (size_t)s * HFF);
        float4 x0 = r[lane];
        float4 x1 = r[32 + lane];
        acc0.x += a0 * x0.x; acc0.y += a0 * x0.y; acc0.z += a0 * x0.z; acc0.w += a0 * x0.w;
        acc1.x += a1 * x1.x; acc1.y += a1 * x1.y; acc1.z += a1 * x1.z; acc1.w += a1 * x1.w;
    }
    float d0 = __shfl_sync(0xffffffffu, den, h0);
    float d1 = __shfl_sync(0xffffffffu, den, h1);
    float i0 = (end > beg) ? 1.f / d0 : 0.f;
    float i1 = (end > beg) ? 1.f / d1 : 0.f;
    const float* bp = bias + p * HFF;
    float4 b0 = *(const float4*)(bp + (lane << 2));
    float4 b1v = *(const float4*)(bp + 128 + (lane << 2));
    float4 o0, o1;
    o0.x = eluf(acc0.x * i0 + b0.x);  o0.y = eluf(acc0.y * i0 + b0.y);
    o0.z = eluf(acc0.z * i0 + b0.z);  o0.w = eluf(acc0.w * i0 + b0.w);
    o1.x = eluf(acc1.x * i1 + b1v.x); o1.y = eluf(acc1.y * i1 + b1v.y);
    o1.z = eluf(acc1.z * i1 + b1v.z); o1.w = eluf(acc1.w * i1 + b1v.w);
    float4* zr = (float4*)(g_z + ((size_t)p * NN + v) * HFF);
    zr[lane] = o0;
    zr[32 + lane] = o1;
}

// ---------------- semantic attention GEMM (tf32 TC) with fused tanh*W2 + per-p sum --------
// A = g_z [200000][256], B = W1 [256][128]. BM=128 BN=64 BK=16.
#define MSEM (PP * NN)
__global__ __launch_bounds__(256) void gemm_sem_tc(const float* __restrict__ W1,
                                                   const float* __restrict__ b1,
                                                   const float* __restrict__ W2) {
    __shared__ uint32_t As[16][136];
    __shared__ uint32_t Bs[16][72];
    __shared__ float spsum[PP];

    int tid = threadIdx.x;
    int warp = tid >> 5, lane = tid & 31;
    int group = lane >> 2, tid4 = lane & 3;
    int warp_m = (warp >> 1) * 32, warp_n = (warp & 1) * 32;
    int m0 = blockIdx.x * 128, n0 = blockIdx.y * 64;

    if (tid < PP) spsum[tid] = 0.f;

    int mA = tid >> 2, kA = (tid & 3) << 2;
    int kB = tid >> 4, nB = (tid & 15) << 2;

    float acc[2][4][4] = {};
    const float* A = g_z;

    int rowA0 = m0 + mA;       if (rowA0 >= MSEM) rowA0 = MSEM - 1;
    int rowA1 = m0 + mA + 64;  if (rowA1 >= MSEM) rowA1 = MSEM - 1;

    for (int k0 = 0; k0 < HFF; k0 += 16) {
        float4 a0 = *(const float4*)(A + (size_t)rowA0 * HFF + k0 + kA);
        float4 a1 = *(const float4*)(A + (size_t)rowA1 * HFF + k0 + kA);
        float4 bv = *(const float4*)(W1 + (size_t)(k0 + kB) * HSS + n0 + nB);
        __syncthreads();
        As[kA + 0][mA] = f2tf32(a0.x); As[kA + 1][mA] = f2tf32(a0.y);
        As[kA + 2][mA] = f2tf32(a0.z); As[kA + 3][mA] = f2tf32(a0.w);
        As[kA + 0][mA + 64] = f2tf32(a1.x); As[kA + 1][mA + 64] = f2tf32(a1.y);
        As[kA + 2][mA + 64] = f2tf32(a1.z); As[kA + 3][mA + 64] = f2tf32(a1.w);
        Bs[kB][nB + 0] = f2tf32(bv.x); Bs[kB][nB + 1] = f2tf32(bv.y);
        Bs[kB][nB + 2] = f2tf32(bv.z); Bs[kB][nB + 3] = f2tf32(bv.w);
        __syncthreads();
        #pragma unroll
        for (int kk = 0; kk < 16; kk += 8) {
            uint32_t af[2][4], bf[4][2];
            #pragma unroll
            for (int mi = 0; mi < 2; mi++) {
                int r0 = warp_m + mi * 16 + group;
                af[mi][0] = As[kk + tid4][r0];
                af[mi][1] = As[kk + tid4][r0 + 8];
                af[mi][2] = As[kk + tid4 + 4][r0];
                af[mi][3] = As[kk + tid4 + 4][r0 + 8];
            }
            #pragma unroll
            for (int ni = 0; ni < 4; ni++) {
                int cc = warp_n + ni * 8 + group;
                bf[ni][0] = Bs[kk + tid4][cc];
                bf[ni][1] = Bs[kk + tid4 + 4][cc];
            }
            #pragma unroll
            for (int mi = 0; mi < 2; mi++)
                #pragma unroll
                for (int ni = 0; ni < 4; ni++)
                    mma_tf32(acc[mi][ni], af[mi], bf[ni]);
        }
    }

    // epilogue: per-row s = sum_cols tanh(c + b1) * W2, reduced over quad, atomic to spsum
    __syncthreads();
    #pragma unroll
    for (int mi = 0; mi < 2; mi++) {
        float s_lo = 0.f, s_hi = 0.f;  // rows group / group+8
        #pragma unroll
        for (int ni = 0; ni < 4; ni++) {
            int col = n0 + warp_n + ni * 8 + (tid4 << 1);
            float bb0 = b1[col], bb1 = b1[col + 1];
            float w0 = W2[col], w1 = W2[col + 1];
            s_lo += tanhf(acc[mi][ni][0] + bb0) * w0 + tanhf(acc[mi][ni][1] + bb1) * w1;
            s_hi += tanhf(acc[mi][ni][2] + bb0) * w0 + tanhf(acc[mi][ni][3] + bb1) * w1;
        }
        // reduce over tid4 (lanes group*4 + {0..3})
        #pragma unroll
        for (int d = 1; d < 4; d <<= 1) {
            s_lo += __shfl_xor_sync(0xffffffffu, s_lo, d);
            s_hi += __shfl_xor_sync(0xffffffffu, s_hi, d);
        }
        if (tid4 == 0) {
            int r0 = m0 + warp_m + mi * 16 + group;
            if (r0 < MSEM)     atomicAdd(&spsum[r0 / NN], s_lo);
            if (r0 + 8 < MSEM) atomicAdd(&spsum[(r0 + 8) / NN], s_hi);
        }
    }
    __syncthreads();
    if (tid < PP) atomicAdd(&g_wsum[tid], spsum[tid]);
}

// ---------------- beta softmax ----------------
__global__ void beta_kernel() {
    if (threadIdx.x == 0 && blockIdx.x == 0) {
        float w[PP], m = -1e30f, s = 0.f;
        #pragma unroll
        for (int p = 0; p < PP; p++) { w[p] = g_wsum[p] / (float)NN; m = fmaxf(m, w[p]); }
        #pragma unroll
        for (int p = 0; p < PP; p++) { w[p] = __expf(w[p] - m); s += w[p]; }
        #pragma unroll
        for (int p = 0; p < PP; p++) g_beta[p] = w[p] / s;
    }
}

// ---------------- fused embedding + per-graph pooling ----------------
__global__ __launch_bounds__(256) void fuse_pool(const int* __restrict__ gids) {
    int n = blockIdx.x * 4 + (threadIdx.x >> 6);
    int t = threadIdx.x & 63;
    if (n >= NN) return;
    int g = gids[n];
    float bb0 = g_beta[0], bb1 = g_beta[1], bb2 = g_beta[2], bb3 = g_beta[3];
    float4 v0 = ((const float4*)(g_z + ((size_t)0 * NN + n) * HFF))[t];
    float4 v1 = ((const float4*)(g_z + ((size_t)1 * NN + n) * HFF))[t];
    float4 v2 = ((const float4*)(g_z + ((size_t)2 * NN + n) * HFF))[t];
    float4 v3 = ((const float4*)(g_z + ((size_t)3 * NN + n) * HFF))[t];
    float4 f;
    f.x = bb0 * v0.x + bb1 * v1.x + bb2 * v2.x + bb3 * v3.x;
    f.y = bb0 * v0.y + bb1 * v1.y + bb2 * v2.y + bb3 * v3.y;
    f.z = bb0 * v0.z + bb1 * v1.z + bb2 * v2.z + bb3 * v3.z;
    f.w = bb0 * v0.w + bb1 * v1.w + bb2 * v2.w + bb3 * v3.w;
    float* dp = g_pooled + g * HFF + (t << 2);
    atomicAdd(dp + 0, f.x);
    atomicAdd(dp + 1, f.y);
    atomicAdd(dp + 2, f.z);
    atomicAdd(dp + 3, f.w);
    if (t == 0) atomicAdd(&g_cnt[g], 1);
}

// ---------------- pooled normalize + classifier ----------------
__global__ __launch_bounds__(256) void final_kernel(const float* __restrict__ clsW,
                                                    const float* __restrict__ clsb,
                                                    float* __restrict__ out) {
    int g = blockIdx.x;
    int t = threadIdx.x;
    float cnt = (float)g_cnt[g];
    float inv = 1.f / fmaxf(cnt, 1.f);
    float pv = g_pooled[g * HFF + t] * inv;
    out[BB * OUTC + g * HFF + t] = pv;
    __shared__ float s0[256], s1[256];
    s0[t] = pv * clsW[t * OUTC + 0];
    s1[t] = pv * clsW[t * OUTC + 1];
    __syncthreads();
    for (int d = 128; d > 0; d >>= 1) {
        if (t < d) { s0[t] += s0[t + d]; s1[t] += s1[t + d]; }
        __syncthreads();
    }
    if (t == 0) {
        out[g * OUTC + 0] = s0[0] + clsb[0];
        out[g * OUTC + 1] = s1[0] + clsb[1];
    }
}

// ---------------- launch ----------------
extern "C" void kernel_launch(void* const* d_in, const int* in_sizes, int n_in,
                              void* d_out, int out_size) {
    const float* h    = (const float*)d_in[0];
    const float* Wg   = (const float*)d_in[1];
    const float* al   = (const float*)d_in[2];
    const float* ar   = (const float*)d_in[3];
    const float* gb   = (const float*)d_in[4];
    const float* sW1  = (const float*)d_in[5];
    const float* sb1  = (const float*)d_in[6];
    const float* sW2  = (const float*)d_in[7];
    const float* cW   = (const float*)d_in[8];
    const float* cb   = (const float*)d_in[9];
    const int*   src  = (const int*)d_in[10];
    const int*   dst  = (const int*)d_in[11];
    const int*   gid  = (const int*)d_in[12];
    float* out = (float*)d_out;

    zero_kernel<<<(PP * NN + 255) / 256, 256>>>();
    deg_kernel<<<(PP * EE + 255) / 256, 256>>>(dst);
    scan_kernel<<<PP, 1024>>>();
    fill_kernel<<<(PP * EE + 255) / 256, 256>>>(src, dst);

    dim3 gp((NN + 127) / 128, HFF / 64, PP);
    gemm_proj_tc<<<gp, 256>>>(h, Wg);

    eler_kernel<<<(PP * NN * HH + 255) / 256, 256>>>(al, ar);

    dim3 ga((NN + 7) / 8, PP);
    attn_kernel<<<ga, 256>>>(gb);

    dim3 gs((PP * NN + 127) / 128, HSS / 64);
    gemm_sem_tc<<<gs, 256>>>(sW1, sb1, sW2);

    beta_kernel<<<1, 32>>>();
    fuse_pool<<<(NN + 3) / 4, 256>>>(gid);
    final_kernel<<<BB, 256>>>(cW, cb, out);
}

// round 3
// speedup vs baseline: 1.9921x; 1.4491x over previous
#include <cuda_runtime.h>
#include <cstdint>

#define NN   50000
#define PP   4
#define EE   500000
#define IND  128
#define HH   8
#define FF   32
#define HFF  256
#define HSS  128
#define BB   128
#define OUTC 2
#define MSEM (PP * NN)

// ---------------- persistent device scratch ----------------
__device__ float g_hp[PP * NN * HFF];
__device__ float g_z[PP * NN * HFF];
__device__ float g_el[PP * NN * HH];
__device__ float g_er[PP * NN * HH];
__device__ int   g_deg[PP * NN];
__device__ int   g_off[PP * (NN + 1)];
__device__ int   g_cur[PP * NN];
__device__ int   g_csr[PP * EE];
__device__ float g_wsum[PP];
__device__ float g_beta[PP];
__device__ float g_pooled[BB * HFF];
__device__ int   g_cnt[BB];

__device__ __forceinline__ float eluf(float x) {
    return x > 0.f ? x : (__expf(x) - 1.f);
}

__device__ __forceinline__ uint32_t f2tf32(float x) {
    uint32_t y;
    asm("cvt.rna.tf32.f32 %0, %1;" : "=r"(y) : "f"(x));
    return y;
}

__device__ __forceinline__ void mma_tf32(float* c, const uint32_t* a, const uint32_t* b) {
    asm volatile(
        "mma.sync.aligned.m16n8k8.row.col.f32.tf32.tf32.f32 "
        "{%0,%1,%2,%3},{%4,%5,%6,%7},{%8,%9},{%0,%1,%2,%3};"
        : "+f"(c[0]), "+f"(c[1]), "+f"(c[2]), "+f"(c[3])
        : "r"(a[0]), "r"(a[1]), "r"(a[2]), "r"(a[3]), "r"(b[0]), "r"(b[1]));
}

// ---------------- init ----------------
__global__ void zero_kernel() {
    int i = blockIdx.x * blockDim.x + threadIdx.x;
    if (i < PP * NN)  g_deg[i] = 0;
    if (i < BB * HFF) g_pooled[i] = 0.f;
    if (i < BB)       g_cnt[i] = 0;
    if (i < PP)       g_wsum[i] = 0.f;
}

// ---------------- CSR build ----------------
__global__ void deg_kernel(const int* __restrict__ dst) {
    int i = blockIdx.x * blockDim.x + threadIdx.x;
    if (i >= PP * EE) return;
    int p = i / EE;
    atomicAdd(&g_deg[p * NN + dst[i]], 1);
}

__global__ void scan_kernel() {
    int p = blockIdx.x;
    __shared__ int wsums[32];
    __shared__ int carry;
    int tid = threadIdx.x, lane = tid & 31, wid = tid >> 5;
    if (tid == 0) { carry = 0; g_off[p * (NN + 1)] = 0; }
    __syncthreads();
    for (int base = 0; base < NN; base += 1024) {
        int i = base + tid;
        int v = (i < NN) ? g_deg[p * NN + i] : 0;
        int x = v;
        #pragma unroll
        for (int d = 1; d < 32; d <<= 1) {
            int t2 = __shfl_up_sync(0xffffffffu, x, d);
            if (lane >= d) x += t2;
        }
        if (lane == 31) wsums[wid] = x;
        __syncthreads();
        if (wid == 0) {
            int y = wsums[lane];
            #pragma unroll
            for (int d = 1; d < 32; d <<= 1) {
                int t2 = __shfl_up_sync(0xffffffffu, y, d);
                if (lane >= d) y += t2;
            }
            wsums[lane] = y;
        }
        __syncthreads();
        int incl = x + (wid ? wsums[wid - 1] : 0) + carry;
        if (i < NN) {
            g_off[p * (NN + 1) + i + 1] = incl;
            g_cur[p * NN + i] = incl - v;
        }
        __syncthreads();
        if (tid == 0) carry += wsums[31];
        __syncthreads();
    }
}

__global__ void fill_kernel(const int* __restrict__ src, const int* __restrict__ dst) {
    int i = blockIdx.x * blockDim.x + threadIdx.x;
    if (i >= PP * EE) return;
    int p = i / EE;
    int d = dst[i];
    int slot = atomicAdd(&g_cur[p * NN + d], 1);
    g_csr[p * EE + slot] = src[i];
}

// ---------------- projection GEMM + fused el/er epilogue ----------------
// BM=128 BN=128 BK=16, 8 warps (2x4), warp tile 64x32 via m16n8k8 tf32.
// Each warp's 32 cols lie within one head => complete el/er dots, no atomics.
__global__ __launch_bounds__(256, 2) void gemm_proj_tc(const float* __restrict__ A,
                                                       const float* __restrict__ Wg,
                                                       const float* __restrict__ al,
                                                       const float* __restrict__ ar) {
    int p = blockIdx.z;
    const float* B = Wg + (size_t)p * IND * HFF;
    float* C = g_hp + (size_t)p * NN * HFF;

    __shared__ uint32_t As[128][20];   // [m][k], pad 20: frag loads conflict-free
    __shared__ uint32_t Bs[16][136];   // [k][n]

    int tid = threadIdx.x;
    int warp = tid >> 5, lane = tid & 31;
    int group = lane >> 2, tid4 = lane & 3;
    int warp_m = (warp >> 2) * 64, warp_n = (warp & 3) * 32;
    int m0 = blockIdx.x * 128, n0 = blockIdx.y * 128;

    int mA = tid >> 2, kA = (tid & 3) << 2;
    int kB = tid >> 5, nB = (tid & 31) << 2;

    float acc[4][4][4] = {};

    int rowA0 = m0 + mA;       if (rowA0 >= NN) rowA0 = NN - 1;
    int rowA1 = m0 + mA + 64;  if (rowA1 >= NN) rowA1 = NN - 1;

    for (int k0 = 0; k0 < IND; k0 += 16) {
        float4 a0 = *(const float4*)(A + (size_t)rowA0 * IND + k0 + kA);
        float4 a1 = *(const float4*)(A + (size_t)rowA1 * IND + k0 + kA);
        float4 b0 = *(const float4*)(B + (size_t)(k0 + kB) * HFF + n0 + nB);
        float4 b1 = *(const float4*)(B + (size_t)(k0 + kB + 8) * HFF + n0 + nB);
        __syncthreads();
        {
            uint4 u0 = {f2tf32(a0.x), f2tf32(a0.y), f2tf32(a0.z), f2tf32(a0.w)};
            uint4 u1 = {f2tf32(a1.x), f2tf32(a1.y), f2tf32(a1.z), f2tf32(a1.w)};
            *(uint4*)&As[mA][kA] = u0;
            *(uint4*)&As[mA + 64][kA] = u1;
            uint4 v0 = {f2tf32(b0.x), f2tf32(b0.y), f2tf32(b0.z), f2tf32(b0.w)};
            uint4 v1 = {f2tf32(b1.x), f2tf32(b1.y), f2tf32(b1.z), f2tf32(b1.w)};
            *(uint4*)&Bs[kB][nB] = v0;
            *(uint4*)&Bs[kB + 8][nB] = v1;
        }
        __syncthreads();
        #pragma unroll
        for (int kk = 0; kk < 16; kk += 8) {
            uint32_t af[4][4], bf[4][2];
            #pragma unroll
            for (int mi = 0; mi < 4; mi++) {
                int r0 = warp_m + mi * 16 + group;
                af[mi][0] = As[r0][kk + tid4];
                af[mi][1] = As[r0 + 8][kk + tid4];
                af[mi][2] = As[r0][kk + tid4 + 4];
                af[mi][3] = As[r0 + 8][kk + tid4 + 4];
            }
            #pragma unroll
            for (int ni = 0; ni < 4; ni++) {
                int cc = warp_n + ni * 8 + group;
                bf[ni][0] = Bs[kk + tid4][cc];
                bf[ni][1] = Bs[kk + tid4 + 4][cc];
            }
            #pragma unroll
            for (int mi = 0; mi < 4; mi++)
                #pragma unroll
                for (int ni = 0; ni < 4; ni++)
                    mma_tf32(acc[mi][ni], af[mi], bf[ni]);
        }
    }

    // store hp
    #pragma unroll
    for (int mi = 0; mi < 4; mi++) {
        int r_lo = m0 + warp_m + mi * 16 + group;
        #pragma unroll
        for (int ni = 0; ni < 4; ni++) {
            int col = n0 + warp_n + ni * 8 + (tid4 << 1);
            if (r_lo < NN) {
                float2 o = {acc[mi][ni][0], acc[mi][ni][1]};
                *(float2*)(C + (size_t)r_lo * HFF + col) = o;
            }
            if (r_lo + 8 < NN) {
                float2 o = {acc[mi][ni][2], acc[mi][ni][3]};
                *(float2*)(C + (size_t)(r_lo + 8) * HFF + col) = o;
            }
        }
    }

    // fused el/er epilogue: this warp's head
    int head = blockIdx.y * 4 + (warp_n >> 5);
    const float* alh = al + p * HFF + head * FF;
    const float* arh = ar + p * HFF + head * FF;
    #pragma unroll
    for (int mi = 0; mi < 4; mi++) {
        float el_lo = 0.f, el_hi = 0.f, er_lo = 0.f, er_hi = 0.f;
        #pragma unroll
        for (int ni = 0; ni < 4; ni++) {
            int f = ni * 8 + (tid4 << 1);
            float a0 = alh[f], a1 = alh[f + 1];
            float r0 = arh[f], r1 = arh[f + 1];
            el_lo += acc[mi][ni][0] * a0 + acc[mi][ni][1] * a1;
            er_lo += acc[mi][ni][0] * r0 + acc[mi][ni][1] * r1;
            el_hi += acc[mi][ni][2] * a0 + acc[mi][ni][3] * a1;
            er_hi += acc[mi][ni][2] * r0 + acc[mi][ni][3] * r1;
        }
        #pragma unroll
        for (int d = 1; d < 4; d <<= 1) {
            el_lo += __shfl_xor_sync(0xffffffffu, el_lo, d);
            er_lo += __shfl_xor_sync(0xffffffffu, er_lo, d);
            el_hi += __shfl_xor_sync(0xffffffffu, el_hi, d);
            er_hi += __shfl_xor_sync(0xffffffffu, er_hi, d);
        }
        if (tid4 == 0) {
            int r = m0 + warp_m + mi * 16 + group;
            if (r < NN) {
                g_el[((size_t)p * NN + r) * HH + head] = el_lo;
                g_er[((size_t)p * NN + r) * HH + head] = er_lo;
            }
            if (r + 8 < NN) {
                g_el[((size_t)p * NN + r + 8) * HH + head] = el_hi;
                g_er[((size_t)p * NN + r + 8) * HH + head] = er_hi;
            }
        }
    }
}

// ---------------- GAT edge softmax + aggregation (single pass, no max) ----------------
__global__ __launch_bounds__(256) void attn_kernel(const float* __restrict__ bias) {
    int lane = threadIdx.x & 31;
    int v = blockIdx.x * 8 + (threadIdx.x >> 5);
    if (v >= NN) return;
    int p = blockIdx.y;
    int beg = g_off[p * (NN + 1) + v];
    int end = g_off[p * (NN + 1) + v + 1];
    const float* __restrict__ elp = g_el + (size_t)p * NN * HH;
    const float* __restrict__ hpp = g_hp + (size_t)p * NN * HFF;
    const int*   __restrict__ csr = g_csr + (size_t)p * EE;
    float er_l = 0.f;
    if (lane < HH) er_l = g_er[(size_t)p * NN * HH + (size_t)v * HH + lane];
    int h0 = lane >> 3, h1 = 4 + (lane >> 3);
    float den = 0.f;
    float4 acc0 = {0, 0, 0, 0}, acc1 = {0, 0, 0, 0};
    for (int i = beg; i < end; i++) {
        int s = csr[i];
        float a = 0.f;
        if (lane < HH) {
            float e = elp[(size_t)s * HH + lane] + er_l;
            e = e > 0.f ? e : 0.2f * e;
            a = __expf(e);
            den += a;
        }
        float a0 = __shfl_sync(0xffffffffu, a, h0);
        float a1 = __shfl_sync(0xffffffffu, a, h1);
        const float4* r = (const float4*)(hpp + (size_t)s * HFF);
        float4 x0 = r[lane];
        float4 x1 = r[32 + lane];
        acc0.x += a0 * x0.x; acc0.y += a0 * x0.y; acc0.z += a0 * x0.z; acc0.w += a0 * x0.w;
        acc1.x += a1 * x1.x; acc1.y += a1 * x1.y; acc1.z += a1 * x1.z; acc1.w += a1 * x1.w;
    }
    float d0 = __shfl_sync(0xffffffffu, den, h0);
    float d1 = __shfl_sync(0xffffffffu, den, h1);
    float i0 = (end > beg) ? 1.f / d0 : 0.f;
    float i1 = (end > beg) ? 1.f / d1 : 0.f;
    const float* bp = bias + p * HFF;
    float4 b0 = *(const float4*)(bp + (lane << 2));
    float4 b1v = *(const float4*)(bp + 128 + (lane << 2));
    float4 o0, o1;
    o0.x = eluf(acc0.x * i0 + b0.x);  o0.y = eluf(acc0.y * i0 + b0.y);
    o0.z = eluf(acc0.z * i0 + b0.z);  o0.w = eluf(acc0.w * i0 + b0.w);
    o1.x = eluf(acc1.x * i1 + b1v.x); o1.y = eluf(acc1.y * i1 + b1v.y);
    o1.z = eluf(acc1.z * i1 + b1v.z); o1.w = eluf(acc1.w * i1 + b1v.w);
    float4* zr = (float4*)(g_z + ((size_t)p * NN + v) * HFF);
    zr[lane] = o0;
    zr[32 + lane] = o1;
}

// ---------------- semantic attention GEMM (tf32 TC, BN=128=HSS, single A pass) ----------
__global__ __launch_bounds__(256, 2) void gemm_sem_tc(const float* __restrict__ W1,
                                                      const float* __restrict__ b1,
                                                      const float* __restrict__ W2) {
    __shared__ uint32_t As[128][20];
    __shared__ uint32_t Bs[16][136];
    __shared__ float spsum[PP];

    int tid = threadIdx.x;
    int warp = tid >> 5, lane = tid & 31;
    int group = lane >> 2, tid4 = lane & 3;
    int warp_m = (warp >> 2) * 64, warp_n = (warp & 3) * 32;
    int m0 = blockIdx.x * 128;

    if (tid < PP) spsum[tid] = 0.f;

    int mA = tid >> 2, kA = (tid & 3) << 2;
    int kB = tid >> 5, nB = (tid & 31) << 2;

    float acc[4][4][4] = {};
    const float* A = g_z;

    int rowA0 = m0 + mA;       if (rowA0 >= MSEM) rowA0 = MSEM - 1;
    int rowA1 = m0 + mA + 64;  if (rowA1 >= MSEM) rowA1 = MSEM - 1;

    for (int k0 = 0; k0 < HFF; k0 += 16) {
        float4 a0 = *(const float4*)(A + (size_t)rowA0 * HFF + k0 + kA);
        float4 a1 = *(const float4*)(A + (size_t)rowA1 * HFF + k0 + kA);
        float4 b0 = *(const float4*)(W1 + (size_t)(k0 + kB) * HSS + nB);
        float4 b1v = *(const float4*)(W1 + (size_t)(k0 + kB + 8) * HSS + nB);
        __syncthreads();
        {
            uint4 u0 = {f2tf32(a0.x), f2tf32(a0.y), f2tf32(a0.z), f2tf32(a0.w)};
            uint4 u1 = {f2tf32(a1.x), f2tf32(a1.y), f2tf32(a1.z), f2tf32(a1.w)};
            *(uint4*)&As[mA][kA] = u0;
            *(uint4*)&As[mA + 64][kA] = u1;
            uint4 v0 = {f2tf32(b0.x), f2tf32(b0.y), f2tf32(b0.z), f2tf32(b0.w)};
            uint4 v1 = {f2tf32(b1v.x), f2tf32(b1v.y), f2tf32(b1v.z), f2tf32(b1v.w)};
            *(uint4*)&Bs[kB][nB] = v0;
            *(uint4*)&Bs[kB + 8][nB] = v1;
        }
        __syncthreads();
        #pragma unroll
        for (int kk = 0; kk < 16; kk += 8) {
            uint32_t af[4][4], bf[4][2];
            #pragma unroll
            for (int mi = 0; mi < 4; mi++) {
                int r0 = warp_m + mi * 16 + group;
                af[mi][0] = As[r0][kk + tid4];
                af[mi][1] = As[r0 + 8][kk + tid4];
                af[mi][2] = As[r0][kk + tid4 + 4];
                af[mi][3] = As[r0 + 8][kk + tid4 + 4];
            }
            #pragma unroll
            for (int ni = 0; ni < 4; ni++) {
                int cc = warp_n + ni * 8 + group;
                bf[ni][0] = Bs[kk + tid4][cc];
                bf[ni][1] = Bs[kk + tid4 + 4][cc];
            }
            #pragma unroll
            for (int mi = 0; mi < 4; mi++)
                #pragma unroll
                for (int ni = 0; ni < 4; ni++)
                    mma_tf32(acc[mi][ni], af[mi], bf[ni]);
        }
    }

    // epilogue: row partial s = sum tanh(c + b1) * W2 over this warp's 32 cols
    #pragma unroll
    for (int mi = 0; mi < 4; mi++) {
        float s_lo = 0.f, s_hi = 0.f;
        #pragma unroll
        for (int ni = 0; ni < 4; ni++) {
            int col = warp_n + ni * 8 + (tid4 << 1);
            float bb0 = b1[col], bb1 = b1[col + 1];
            float w0 = W2[col], w1 = W2[col + 1];
            s_lo += tanhf(acc[mi][ni][0] + bb0) * w0 + tanhf(acc[mi][ni][1] + bb1) * w1;
            s_hi += tanhf(acc[mi][ni][2] + bb0) * w0 + tanhf(acc[mi][ni][3] + bb1) * w1;
        }
        #pragma unroll
        for (int d = 1; d < 4; d <<= 1) {
            s_lo += __shfl_xor_sync(0xffffffffu, s_lo, d);
            s_hi += __shfl_xor_sync(0xffffffffu, s_hi, d);
        }
        if (tid4 == 0) {
            int r = m0 + warp_m + mi * 16 + group;
            if (r < MSEM)     atomicAdd(&spsum[r / NN], s_lo);
            if (r + 8 < MSEM) atomicAdd(&spsum[(r + 8) / NN], s_hi);
        }
    }
    __syncthreads();
    if (tid < PP) atomicAdd(&g_wsum[tid], spsum[tid]);
}

// ---------------- beta softmax ----------------
__global__ void beta_kernel() {
    if (threadIdx.x == 0 && blockIdx.x == 0) {
        float w[PP], m = -1e30f, s = 0.f;
        #pragma unroll
        for (int p = 0; p < PP; p++) { w[p] = g_wsum[p] / (float)NN; m = fmaxf(m, w[p]); }
        #pragma unroll
        for (int p = 0; p < PP; p++) { w[p] = __expf(w[p] - m); s += w[p]; }
        #pragma unroll
        for (int p = 0; p < PP; p++) g_beta[p] = w[p] / s;
    }
}

// ---------------- fused embedding + per-graph pooling ----------------
__global__ __launch_bounds__(256) void fuse_pool(const int* __restrict__ gids) {
    int n = blockIdx.x * 4 + (threadIdx.x >> 6);
    int t = threadIdx.x & 63;
    if (n >= NN) return;
    int g = gids[n];
    float bb0 = g_beta[0], bb1 = g_beta[1], bb2 = g_beta[2], bb3 = g_beta[3];
    float4 v0 = ((const float4*)(g_z + ((size_t)0 * NN + n) * HFF))[t];
    float4 v1 = ((const float4*)(g_z + ((size_t)1 * NN + n) * HFF))[t];
    float4 v2 = ((const float4*)(g_z + ((size_t)2 * NN + n) * HFF))[t];
    float4 v3 = ((const float4*)(g_z + ((size_t)3 * NN + n) * HFF))[t];
    float4 f;
    f.x = bb0 * v0.x + bb1 * v1.x + bb2 * v2.x + bb3 * v3.x;
    f.y = bb0 * v0.y + bb1 * v1.y + bb2 * v2.y + bb3 * v3.y;
    f.z = bb0 * v0.z + bb1 * v1.z + bb2 * v2.z + bb3 * v3.z;
    f.w = bb0 * v0.w + bb1 * v1.w + bb2 * v2.w + bb3 * v3.w;
    float* dp = g_pooled + g * HFF + (t << 2);
    atomicAdd(dp + 0, f.x);
    atomicAdd(dp + 1, f.y);
    atomicAdd(dp + 2, f.z);
    atomicAdd(dp + 3, f.w);
    if (t == 0) atomicAdd(&g_cnt[g], 1);
}

// ---------------- pooled normalize + classifier ----------------
__global__ __launch_bounds__(256) void final_kernel(const float* __restrict__ clsW,
                                                    const float* __restrict__ clsb,
                                                    float* __restrict__ out) {
    int g = blockIdx.x;
    int t = threadIdx.x;
    float cnt = (float)g_cnt[g];
    float inv = 1.f / fmaxf(cnt, 1.f);
    float pv = g_pooled[g * HFF + t] * inv;
    out[BB * OUTC + g * HFF + t] = pv;
    __shared__ float s0[256], s1[256];
    s0[t] = pv * clsW[t * OUTC + 0];
    s1[t] = pv * clsW[t * OUTC + 1];
    __syncthreads();
    for (int d = 128; d > 0; d >>= 1) {
        if (t < d) { s0[t] += s0[t + d]; s1[t] += s1[t + d]; }
        __syncthreads();
    }
    if (t == 0) {
        out[g * OUTC + 0] = s0[0] + clsb[0];
        out[g * OUTC + 1] = s1[0] + clsb[1];
    }
}

// ---------------- launch ----------------
extern "C" void kernel_launch(void* const* d_in, const int* in_sizes, int n_in,
                              void* d_out, int out_size) {
    const float* h    = (const float*)d_in[0];
    const float* Wg   = (const float*)d_in[1];
    const float* al   = (const float*)d_in[2];
    const float* ar   = (const float*)d_in[3];
    const float* gb   = (const float*)d_in[4];
    const float* sW1  = (const float*)d_in[5];
    const float* sb1  = (const float*)d_in[6];
    const float* sW2  = (const float*)d_in[7];
    const float* cW   = (const float*)d_in[8];
    const float* cb   = (const float*)d_in[9];
    const int*   src  = (const int*)d_in[10];
    const int*   dst  = (const int*)d_in[11];
    const int*   gid  = (const int*)d_in[12];
    float* out = (float*)d_out;

    zero_kernel<<<(PP * NN + 255) / 256, 256>>>();
    deg_kernel<<<(PP * EE + 255) / 256, 256>>>(dst);
    scan_kernel<<<PP, 1024>>>();
    fill_kernel<<<(PP * EE + 255) / 256, 256>>>(src, dst);

    dim3 gp((NN + 127) / 128, 2, PP);
    gemm_proj_tc<<<gp, 256>>>(h, Wg, al, ar);

    dim3 ga((NN + 7) / 8, PP);
    attn_kernel<<<ga, 256>>>(gb);

    dim3 gs((MSEM + 127) / 128, 1);
    gemm_sem_tc<<<gs, 256>>>(sW1, sb1, sW2);

    beta_kernel<<<1, 32>>>();
    fuse_pool<<<(NN + 3) / 4, 256>>>(gid);
    final_kernel<<<BB, 256>>>(cW, cb, out);
}

// round 4
// speedup vs baseline: 2.1821x; 1.0954x over previous
#include <cuda_runtime.h>
#include <cuda_fp16.h>
#include <cstdint>

#define NN   50000
#define PP   4
#define EE   500000
#define IND  128
#define HH   8
#define FF   32
#define HFF  256
#define HSS  128
#define BB   128
#define OUTC 2
#define MSEM (PP * NN)

// ---------------- persistent device scratch ----------------
__device__ __half g_hp16[PP * NN * HFF];   // projected features, fp16 (102.4 MB)
__device__ __half g_z16[PP * NN * HFF];    // GAT outputs, fp16 (102.4 MB)
__device__ float g_el[PP * NN * HH];
__device__ float g_er[PP * NN * HH];
__device__ int   g_deg[PP * NN];
__device__ int   g_off[PP * (NN + 1)];
__device__ int   g_cur[PP * NN];
__device__ int   g_csr[PP * EE];
__device__ float g_wsum[PP];
__device__ float g_beta[PP];
__device__ float g_pooled[BB * HFF];
__device__ int   g_cnt[BB];

__device__ __forceinline__ float eluf(float x) {
    return x > 0.f ? x : (__expf(x) - 1.f);
}

__device__ __forceinline__ uint32_t f2tf32(float x) {
    uint32_t y;
    asm("cvt.rna.tf32.f32 %0, %1;" : "=r"(y) : "f"(x));
    return y;
}

__device__ __forceinline__ void mma_tf32(float* c, const uint32_t* a, const uint32_t* b) {
    asm volatile(
        "mma.sync.aligned.m16n8k8.row.col.f32.tf32.tf32.f32 "
        "{%0,%1,%2,%3},{%4,%5,%6,%7},{%8,%9},{%0,%1,%2,%3};"
        : "+f"(c[0]), "+f"(c[1]), "+f"(c[2]), "+f"(c[3])
        : "r"(a[0]), "r"(a[1]), "r"(a[2]), "r"(a[3]), "r"(b[0]), "r"(b[1]));
}

// ---------------- init ----------------
__global__ void zero_kernel() {
    int i = blockIdx.x * blockDim.x + threadIdx.x;
    if (i < PP * NN)  g_deg[i] = 0;
    if (i < BB * HFF) g_pooled[i] = 0.f;
    if (i < BB)       g_cnt[i] = 0;
    if (i < PP)       g_wsum[i] = 0.f;
}

__global__ void cnt_kernel(const int* __restrict__ gids) {
    int i = blockIdx.x * blockDim.x + threadIdx.x;
    if (i < NN) atomicAdd(&g_cnt[gids[i]], 1);
}

// ---------------- CSR build ----------------
__global__ void deg_kernel(const int* __restrict__ dst) {
    int i = blockIdx.x * blockDim.x + threadIdx.x;
    if (i >= PP * EE) return;
    int p = i / EE;
    atomicAdd(&g_deg[p * NN + dst[i]], 1);
}

__global__ void scan_kernel() {
    int p = blockIdx.x;
    __shared__ int wsums[32];
    __shared__ int carry;
    int tid = threadIdx.x, lane = tid & 31, wid = tid >> 5;
    if (tid == 0) { carry = 0; g_off[p * (NN + 1)] = 0; }
    __syncthreads();
    for (int base = 0; base < NN; base += 1024) {
        int i = base + tid;
        int v = (i < NN) ? g_deg[p * NN + i] : 0;
        int x = v;
        #pragma unroll
        for (int d = 1; d < 32; d <<= 1) {
            int t2 = __shfl_up_sync(0xffffffffu, x, d);
            if (lane >= d) x += t2;
        }
        if (lane == 31) wsums[wid] = x;
        __syncthreads();
        if (wid == 0) {
            int y = wsums[lane];
            #pragma unroll
            for (int d = 1; d < 32; d <<= 1) {
                int t2 = __shfl_up_sync(0xffffffffu, y, d);
                if (lane >= d) y += t2;
            }
            wsums[lane] = y;
        }
        __syncthreads();
        int incl = x + (wid ? wsums[wid - 1] : 0) + carry;
        if (i < NN) {
            g_off[p * (NN + 1) + i + 1] = incl;
            g_cur[p * NN + i] = incl - v;
        }
        __syncthreads();
        if (tid == 0) carry += wsums[31];
        __syncthreads();
    }
}

__global__ void fill_kernel(const int* __restrict__ src, const int* __restrict__ dst) {
    int i = blockIdx.x * blockDim.x + threadIdx.x;
    if (i >= PP * EE) return;
    int p = i / EE;
    int d = dst[i];
    int slot = atomicAdd(&g_cur[p * NN + d], 1);
    g_csr[p * EE + slot] = src[i];
}

// ---------------- projection GEMM + fused el/er epilogue ----------------
// BM=128 BN=128 BK=16, 8 warps (2x4), warp tile 64x32 via m16n8k8 tf32.
__global__ __launch_bounds__(256, 2) void gemm_proj_tc(const float* __restrict__ A,
                                                       const float* __restrict__ Wg,
                                                       const float* __restrict__ al,
                                                       const float* __restrict__ ar) {
    int p = blockIdx.z;
    const float* B = Wg + (size_t)p * IND * HFF;
    __half* C = g_hp16 + (size_t)p * NN * HFF;

    __shared__ uint32_t As[128][20];
    __shared__ uint32_t Bs[16][136];

    int tid = threadIdx.x;
    int warp = tid >> 5, lane = tid & 31;
    int group = lane >> 2, tid4 = lane & 3;
    int warp_m = (warp >> 2) * 64, warp_n = (warp & 3) * 32;
    int m0 = blockIdx.x * 128, n0 = blockIdx.y * 128;

    int mA = tid >> 2, kA = (tid & 3) << 2;
    int kB = tid >> 5, nB = (tid & 31) << 2;

    float acc[4][4][4] = {};

    int rowA0 = m0 + mA;       if (rowA0 >= NN) rowA0 = NN - 1;
    int rowA1 = m0 + mA + 64;  if (rowA1 >= NN) rowA1 = NN - 1;

    for (int k0 = 0; k0 < IND; k0 += 16) {
        float4 a0 = *(const float4*)(A + (size_t)rowA0 * IND + k0 + kA);
        float4 a1 = *(const float4*)(A + (size_t)rowA1 * IND + k0 + kA);
        float4 b0 = *(const float4*)(B + (size_t)(k0 + kB) * HFF + n0 + nB);
        float4 b1 = *(const float4*)(B + (size_t)(k0 + kB + 8) * HFF + n0 + nB);
        __syncthreads();
        {
            uint4 u0 = {f2tf32(a0.x), f2tf32(a0.y), f2tf32(a0.z), f2tf32(a0.w)};
            uint4 u1 = {f2tf32(a1.x), f2tf32(a1.y), f2tf32(a1.z), f2tf32(a1.w)};
            *(uint4*)&As[mA][kA] = u0;
            *(uint4*)&As[mA + 64][kA] = u1;
            uint4 v0 = {f2tf32(b0.x), f2tf32(b0.y), f2tf32(b0.z), f2tf32(b0.w)};
            uint4 v1 = {f2tf32(b1.x), f2tf32(b1.y), f2tf32(b1.z), f2tf32(b1.w)};
            *(uint4*)&Bs[kB][nB] = v0;
            *(uint4*)&Bs[kB + 8][nB] = v1;
        }
        __syncthreads();
        #pragma unroll
        for (int kk = 0; kk < 16; kk += 8) {
            uint32_t af[4][4], bf[4][2];
            #pragma unroll
            for (int mi = 0; mi < 4; mi++) {
                int r0 = warp_m + mi * 16 + group;
                af[mi][0] = As[r0][kk + tid4];
                af[mi][1] = As[r0 + 8][kk + tid4];
                af[mi][2] = As[r0][kk + tid4 + 4];
                af[mi][3] = As[r0 + 8][kk + tid4 + 4];
            }
            #pragma unroll
            for (int ni = 0; ni < 4; ni++) {
                int cc = warp_n + ni * 8 + group;
                bf[ni][0] = Bs[kk + tid4][cc];
                bf[ni][1] = Bs[kk + tid4 + 4][cc];
            }
            #pragma unroll
            for (int mi = 0; mi < 4; mi++)
                #pragma unroll
                for (int ni = 0; ni < 4; ni++)
                    mma_tf32(acc[mi][ni], af[mi], bf[ni]);
        }
    }

    // store hp as fp16
    #pragma unroll
    for (int mi = 0; mi < 4; mi++) {
        int r_lo = m0 + warp_m + mi * 16 + group;
        #pragma unroll
        for (int ni = 0; ni < 4; ni++) {
            int col = n0 + warp_n + ni * 8 + (tid4 << 1);
            if (r_lo < NN) {
                __half2 o = __floats2half2_rn(acc[mi][ni][0], acc[mi][ni][1]);
                *(__half2*)(C + (size_t)r_lo * HFF + col) = o;
            }
            if (r_lo + 8 < NN) {
                __half2 o = __floats2half2_rn(acc[mi][ni][2], acc[mi][ni][3]);
                *(__half2*)(C + (size_t)(r_lo + 8) * HFF + col) = o;
            }
        }
    }

    // fused el/er epilogue
    int head = blockIdx.y * 4 + (warp_n >> 5);
    const float* alh = al + p * HFF + head * FF;
    const float* arh = ar + p * HFF + head * FF;
    #pragma unroll
    for (int mi = 0; mi < 4; mi++) {
        float el_lo = 0.f, el_hi = 0.f, er_lo = 0.f, er_hi = 0.f;
        #pragma unroll
        for (int ni = 0; ni < 4; ni++) {
            int f = ni * 8 + (tid4 << 1);
            float a0 = alh[f], a1 = alh[f + 1];
            float r0 = arh[f], r1 = arh[f + 1];
            el_lo += acc[mi][ni][0] * a0 + acc[mi][ni][1] * a1;
            er_lo += acc[mi][ni][0] * r0 + acc[mi][ni][1] * r1;
            el_hi += acc[mi][ni][2] * a0 + acc[mi][ni][3] * a1;
            er_hi += acc[mi][ni][2] * r0 + acc[mi][ni][3] * r1;
        }
        #pragma unroll
        for (int d = 1; d < 4; d <<= 1) {
            el_lo += __shfl_xor_sync(0xffffffffu, el_lo, d);
            er_lo += __shfl_xor_sync(0xffffffffu, er_lo, d);
            el_hi += __shfl_xor_sync(0xffffffffu, el_hi, d);
            er_hi += __shfl_xor_sync(0xffffffffu, er_hi, d);
        }
        if (tid4 == 0) {
            int r = m0 + warp_m + mi * 16 + group;
            if (r < NN) {
                g_el[((size_t)p * NN + r) * HH + head] = el_lo;
                g_er[((size_t)p * NN + r) * HH + head] = er_lo;
            }
            if (r + 8 < NN) {
                g_el[((size_t)p * NN + r + 8) * HH + head] = el_hi;
                g_er[((size_t)p * NN + r + 8) * HH + head] = er_hi;
            }
        }
    }
}

// ---------------- GAT edge softmax + aggregation (single pass, fp16 gather) ----------------
// warp per dst node; lane owns 8 contiguous cols (head = lane>>2); one uint4/edge.
__global__ __launch_bounds__(256) void attn_kernel(const float* __restrict__ bias) {
    int lane = threadIdx.x & 31;
    int v = blockIdx.x * 8 + (threadIdx.x >> 5);
    if (v >= NN) return;
    int p = blockIdx.y;
    int beg = g_off[p * (NN + 1) + v];
    int end = g_off[p * (NN + 1) + v + 1];
    const float*  __restrict__ elp = g_el + (size_t)p * NN * HH;
    const __half* __restrict__ hpp = g_hp16 + (size_t)p * NN * HFF;
    const int*    __restrict__ csr = g_csr + (size_t)p * EE;
    float er_l = 0.f;
    if (lane < HH) er_l = g_er[((size_t)p * NN + v) * HH + lane];
    int h = lane >> 2;
    float den = 0.f;
    float acc[8] = {};
    for (int i = beg; i < end; i++) {
        int s = csr[i];
        float a = 0.f;
        if (lane < HH) {
            float e = elp[(size_t)s * HH + lane] + er_l;
            e = e > 0.f ? e : 0.2f * e;
            a = __expf(e);
            den += a;
        }
        float ah = __shfl_sync(0xffffffffu, a, h);
        uint4 raw = *(const uint4*)(hpp + (size_t)s * HFF + (lane << 3));
        float2 f0 = __half22float2(*(__half2*)&raw.x);
        float2 f1 = __half22float2(*(__half2*)&raw.y);
        float2 f2 = __half22float2(*(__half2*)&raw.z);
        float2 f3 = __half22float2(*(__half2*)&raw.w);
        acc[0] += ah * f0.x; acc[1] += ah * f0.y;
        acc[2] += ah * f1.x; acc[3] += ah * f1.y;
        acc[4] += ah * f2.x; acc[5] += ah * f2.y;
        acc[6] += ah * f3.x; acc[7] += ah * f3.y;
    }
    float dh = __shfl_sync(0xffffffffu, den, h);
    float inv = (end > beg) ? 1.f / dh : 0.f;
    const float* bp = bias + p * HFF + (lane << 3);
    float4 b0 = *(const float4*)(bp);
    float4 b1 = *(const float4*)(bp + 4);
    float o0 = eluf(acc[0] * inv + b0.x);
    float o1 = eluf(acc[1] * inv + b0.y);
    float o2 = eluf(acc[2] * inv + b0.z);
    float o3 = eluf(acc[3] * inv + b0.w);
    float o4 = eluf(acc[4] * inv + b1.x);
    float o5 = eluf(acc[5] * inv + b1.y);
    float o6 = eluf(acc[6] * inv + b1.z);
    float o7 = eluf(acc[7] * inv + b1.w);
    uint4 out;
    *(__half2*)&out.x = __floats2half2_rn(o0, o1);
    *(__half2*)&out.y = __floats2half2_rn(o2, o3);
    *(__half2*)&out.z = __floats2half2_rn(o4, o5);
    *(__half2*)&out.w = __floats2half2_rn(o6, o7);
    *(uint4*)(g_z16 + ((size_t)p * NN + v) * HFF + (lane << 3)) = out;
}

// ---------------- semantic attention GEMM (fp16 A -> tf32 TC) ----------
__global__ __launch_bounds__(256, 2) void gemm_sem_tc(const float* __restrict__ W1,
                                                      const float* __restrict__ b1,
                                                      const float* __restrict__ W2) {
    __shared__ uint32_t As[128][20];
    __shared__ uint32_t Bs[16][136];
    __shared__ float spsum[PP];

    int tid = threadIdx.x;
    int warp = tid >> 5, lane = tid & 31;
    int group = lane >> 2, tid4 = lane & 3;
    int warp_m = (warp >> 2) * 64, warp_n = (warp & 3) * 32;
    int m0 = blockIdx.x * 128;

    if (tid < PP) spsum[tid] = 0.f;

    int mA = tid >> 1, kA = (tid & 1) << 3;   // 8 halfs per thread
    int kB = tid >> 5, nB = (tid & 31) << 2;

    float acc[4][4][4] = {};
    const __half* A = g_z16;

    int rowA = m0 + mA;  if (rowA >= MSEM) rowA = MSEM - 1;

    for (int k0 = 0; k0 < HFF; k0 += 16) {
        uint4 araw = *(const uint4*)(A + (size_t)rowA * HFF + k0 + kA);
        float4 b0 = *(const float4*)(W1 + (size_t)(k0 + kB) * HSS + nB);
        float4 b1v = *(const float4*)(W1 + (size_t)(k0 + kB + 8) * HSS + nB);
        __syncthreads();
        {
            float2 f0 = __half22float2(*(__half2*)&araw.x);
            float2 f1 = __half22float2(*(__half2*)&araw.y);
            float2 f2 = __half22float2(*(__half2*)&araw.z);
            float2 f3 = __half22float2(*(__half2*)&araw.w);
            uint4 u0 = {f2tf32(f0.x), f2tf32(f0.y), f2tf32(f1.x), f2tf32(f1.y)};
            uint4 u1 = {f2tf32(f2.x), f2tf32(f2.y), f2tf32(f3.x), f2tf32(f3.y)};
            *(uint4*)&As[mA][kA] = u0;
            *(uint4*)&As[mA][kA + 4] = u1;
            uint4 v0 = {f2tf32(b0.x), f2tf32(b0.y), f2tf32(b0.z), f2tf32(b0.w)};
            uint4 v1 = {f2tf32(b1v.x), f2tf32(b1v.y), f2tf32(b1v.z), f2tf32(b1v.w)};
            *(uint4*)&Bs[kB][nB] = v0;
            *(uint4*)&Bs[kB + 8][nB] = v1;
        }
        __syncthreads();
        #pragma unroll
        for (int kk = 0; kk < 16; kk += 8) {
            uint32_t af[4][4], bf[4][2];
            #pragma unroll
            for (int mi = 0; mi < 4; mi++) {
                int r0 = warp_m + mi * 16 + group;
                af[mi][0] = As[r0][kk + tid4];
                af[mi][1] = As[r0 + 8][kk + tid4];
                af[mi][2] = As[r0][kk + tid4 + 4];
                af[mi][3] = As[r0 + 8][kk + tid4 + 4];
            }
            #pragma unroll
            for (int ni = 0; ni < 4; ni++) {
                int cc = warp_n + ni * 8 + group;
                bf[ni][0] = Bs[kk + tid4][cc];
                bf[ni][1] = Bs[kk + tid4 + 4][cc];
            }
            #pragma unroll
            for (int mi = 0; mi < 4; mi++)
                #pragma unroll
                for (int ni = 0; ni < 4; ni++)
                    mma_tf32(acc[mi][ni], af[mi], bf[ni]);
        }
    }

    #pragma unroll
    for (int mi = 0; mi < 4; mi++) {
        float s_lo = 0.f, s_hi = 0.f;
        #pragma unroll
        for (int ni = 0; ni < 4; ni++) {
            int col = warp_n + ni * 8 + (tid4 << 1);
            float bb0 = b1[col], bb1 = b1[col + 1];
            float w0 = W2[col], w1 = W2[col + 1];
            s_lo += tanhf(acc[mi][ni][0] + bb0) * w0 + tanhf(acc[mi][ni][1] + bb1) * w1;
            s_hi += tanhf(acc[mi][ni][2] + bb0) * w0 + tanhf(acc[mi][ni][3] + bb1) * w1;
        }
        #pragma unroll
        for (int d = 1; d < 4; d <<= 1) {
            s_lo += __shfl_xor_sync(0xffffffffu, s_lo, d);
            s_hi += __shfl_xor_sync(0xffffffffu, s_hi, d);
        }
        if (tid4 == 0) {
            int r = m0 + warp_m + mi * 16 + group;
            if (r < MSEM)     atomicAdd(&spsum[r / NN], s_lo);
            if (r + 8 < MSEM) atomicAdd(&spsum[(r + 8) / NN], s_hi);
        }
    }
    __syncthreads();
    if (tid < PP) atomicAdd(&g_wsum[tid], spsum[tid]);
}

// ---------------- beta softmax ----------------
__global__ void beta_kernel() {
    if (threadIdx.x == 0 && blockIdx.x == 0) {
        float w[PP], m = -1e30f, s = 0.f;
        #pragma unroll
        for (int p = 0; p < PP; p++) { w[p] = g_wsum[p] / (float)NN; m = fmaxf(m, w[p]); }
        #pragma unroll
        for (int p = 0; p < PP; p++) { w[p] = __expf(w[p] - m); s += w[p]; }
        #pragma unroll
        for (int p = 0; p < PP; p++) g_beta[p] = w[p] / s;
    }
}

// ---------------- fused embedding + per-graph pooling (smem-binned) ----------------
// grid (node_chunks, 4 col-slices); block 256. bin[128][64] smem, merge once per block.
#define POOL_CHUNK 1024
__global__ __launch_bounds__(256) void pool_kernel(const int* __restrict__ gids) {
    __shared__ float bin[BB][64];
    int tid = threadIdx.x;
    int cy = blockIdx.y;
    int n0 = blockIdx.x * POOL_CHUNK;
    #pragma unroll
    for (int k = tid; k < BB * 64; k += 256) ((float*)bin)[k] = 0.f;
    __syncthreads();
    float bb0 = g_beta[0], bb1 = g_beta[1], bb2 = g_beta[2], bb3 = g_beta[3];
    int c = (tid & 15) << 2;            // 0..60
    int colg = cy * 64 + c;
    int nend = n0 + POOL_CHUNK; if (nend > NN) nend = NN;
    for (int n = n0 + (tid >> 4); n < nend; n += 16) {
        int g = gids[n];
        uint2 r0 = *(const uint2*)(g_z16 + ((size_t)0 * NN + n) * HFF + colg);
        uint2 r1 = *(const uint2*)(g_z16 + ((size_t)1 * NN + n) * HFF + colg);
        uint2 r2 = *(const uint2*)(g_z16 + ((size_t)2 * NN + n) * HFF + colg);
        uint2 r3 = *(const uint2*)(g_z16 + ((size_t)3 * NN + n) * HFF + colg);
        float2 a0 = __half22float2(*(__half2*)&r0.x), a1 = __half22float2(*(__half2*)&r0.y);
        float2 b0 = __half22float2(*(__half2*)&r1.x), b1 = __half22float2(*(__half2*)&r1.y);
        float2 c0 = __half22float2(*(__half2*)&r2.x), c1 = __half22float2(*(__half2*)&r2.y);
        float2 d0 = __half22float2(*(__half2*)&r3.x), d1 = __half22float2(*(__half2*)&r3.y);
        float f0 = bb0 * a0.x + bb1 * b0.x + bb2 * c0.x + bb3 * d0.x;
        float f1 = bb0 * a0.y + bb1 * b0.y + bb2 * c0.y + bb3 * d0.y;
        float f2 = bb0 * a1.x + bb1 * b1.x + bb2 * c1.x + bb3 * d1.x;
        float f3 = bb0 * a1.y + bb1 * b1.y + bb2 * c1.y + bb3 * d1.y;
        atomicAdd(&bin[g][c + 0], f0);
        atomicAdd(&bin[g][c + 1], f1);
        atomicAdd(&bin[g][c + 2], f2);
        atomicAdd(&bin[g][c + 3], f3);
    }
    __syncthreads();
    for (int k = tid; k < BB * 64; k += 256) {
        int g = k >> 6, cc = k & 63;
        float v = bin[g][cc];
        if (v != 0.f) atomicAdd(&g_pooled[g * HFF + cy * 64 + cc], v);
    }
}

// ---------------- pooled normalize + classifier ----------------
__global__ __launch_bounds__(256) void final_kernel(const float* __restrict__ clsW,
                                                    const float* __restrict__ clsb,
                                                    float* __restrict__ out) {
    int g = blockIdx.x;
    int t = threadIdx.x;
    float cnt = (float)g_cnt[g];
    float inv = 1.f / fmaxf(cnt, 1.f);
    float pv = g_pooled[g * HFF + t] * inv;
    out[BB * OUTC + g * HFF + t] = pv;
    __shared__ float s0[256], s1[256];
    s0[t] = pv * clsW[t * OUTC + 0];
    s1[t] = pv * clsW[t * OUTC + 1];
    __syncthreads();
    for (int d = 128; d > 0; d >>= 1) {
        if (t < d) { s0[t] += s0[t + d]; s1[t] += s1[t + d]; }
        __syncthreads();
    }
    if (t == 0) {
        out[g * OUTC + 0] = s0[0] + clsb[0];
        out[g * OUTC + 1] = s1[0] + clsb[1];
    }
}

// ---------------- launch ----------------
extern "C" void kernel_launch(void* const* d_in, const int* in_sizes, int n_in,
                              void* d_out, int out_size) {
    const float* h    = (const float*)d_in[0];
    const float* Wg   = (const float*)d_in[1];
    const float* al   = (const float*)d_in[2];
    const float* ar   = (const float*)d_in[3];
    const float* gb   = (const float*)d_in[4];
    const float* sW1  = (const float*)d_in[5];
    const float* sb1  = (const float*)d_in[6];
    const float* sW2  = (const float*)d_in[7];
    const float* cW   = (const float*)d_in[8];
    const float* cb   = (const float*)d_in[9];
    const int*   src  = (const int*)d_in[10];
    const int*   dst  = (const int*)d_in[11];
    const int*   gid  = (const int*)d_in[12];
    float* out = (float*)d_out;

    zero_kernel<<<(PP * NN + 255) / 256, 256>>>();
    cnt_kernel<<<(NN + 255) / 256, 256>>>(gid);
    deg_kernel<<<(PP * EE + 255) / 256, 256>>>(dst);
    scan_kernel<<<PP, 1024>>>();
    fill_kernel<<<(PP * EE + 255) / 256, 256>>>(src, dst);

    dim3 gp((NN + 127) / 128, 2, PP);
    gemm_proj_tc<<<gp, 256>>>(h, Wg, al, ar);

    dim3 ga((NN + 7) / 8, PP);
    attn_kernel<<<ga, 256>>>(gb);

    dim3 gs((MSEM + 127) / 128, 1);
    gemm_sem_tc<<<gs, 256>>>(sW1, sb1, sW2);

    beta_kernel<<<1, 32>>>();
    dim3 gpool((NN + POOL_CHUNK - 1) / POOL_CHUNK, 4);
    pool_kernel<<<gpool, 256>>>(gid);
    final_kernel<<<BB, 256>>>(cW, cb, out);
}

// round 5
// speedup vs baseline: 2.4754x; 1.1344x over previous
#include <cuda_runtime.h>
#include <cuda_fp16.h>
#include <cstdint>

#define NN   50000
#define PP   4
#define EE   500000
#define IND  128
#define HH   8
#define FF   32
#define HFF  256
#define HSS  128
#define BB   128
#define OUTC 2
#define MSEM (PP * NN)
#define CH   1024
#define NCH  ((NN + CH - 1) / CH)    // 49

// ---------------- persistent device scratch ----------------
__device__ __half g_hp16[PP * NN * HFF];
__device__ __half g_z16[PP * NN * HFF];
__device__ __half g_W1h[HSS * HFF];        // W1 transposed [n][k], fp16
__device__ float g_el[PP * NN * HH];
__device__ float g_er[PP * NN * HH];
__device__ int   g_deg[PP * NN];
__device__ int   g_off[PP * (NN + 1)];
__device__ int   g_cur[PP * NN];
__device__ int   g_csr[PP * EE];
__device__ int   g_bsum[PP * NCH];
__device__ int   g_boff[PP * NCH];
__device__ float g_wsum[PP];
__device__ float g_beta[PP];
__device__ float g_pooled[BB * HFF];
__device__ int   g_cnt[BB];

__device__ __forceinline__ float eluf(float x) {
    return x > 0.f ? x : (__expf(x) - 1.f);
}

__device__ __forceinline__ uint32_t f2tf32(float x) {
    uint32_t y;
    asm("cvt.rna.tf32.f32 %0, %1;" : "=r"(y) : "f"(x));
    return y;
}

__device__ __forceinline__ void mma_tf32(float* c, const uint32_t* a, const uint32_t* b) {
    asm volatile(
        "mma.sync.aligned.m16n8k8.row.col.f32.tf32.tf32.f32 "
        "{%0,%1,%2,%3},{%4,%5,%6,%7},{%8,%9},{%0,%1,%2,%3};"
        : "+f"(c[0]), "+f"(c[1]), "+f"(c[2]), "+f"(c[3])
        : "r"(a[0]), "r"(a[1]), "r"(a[2]), "r"(a[3]), "r"(b[0]), "r"(b[1]));
}

__device__ __forceinline__ void mma_f16(float* c, uint32_t a0, uint32_t a1, uint32_t b0) {
    asm volatile(
        "mma.sync.aligned.m16n8k8.row.col.f32.f16.f16.f32 "
        "{%0,%1,%2,%3},{%4,%5},{%6},{%0,%1,%2,%3};"
        : "+f"(c[0]), "+f"(c[1]), "+f"(c[2]), "+f"(c[3])
        : "r"(a0), "r"(a1), "r"(b0));
}

// ---------------- init (+ graph node counts) ----------------
__global__ void zero_kernel(const int* __restrict__ gids) {
    int i = blockIdx.x * blockDim.x + threadIdx.x;
    if (i < PP * NN)  g_deg[i] = 0;
    if (i < BB * HFF) g_pooled[i] = 0.f;
    if (i < BB)       g_cnt[i] = 0;
    if (i < PP)       g_wsum[i] = 0.f;
    if (i < NN)       atomicAdd(&g_cnt[gids[i]], 1);
}

// ---------------- W1 transpose to fp16 ----------------
__global__ void w1h_kernel(const float* __restrict__ W1) {
    int i = blockIdx.x * blockDim.x + threadIdx.x;     // i = k*HSS + n
    if (i >= HFF * HSS) return;
    int k = i / HSS, n = i % HSS;
    g_W1h[n * HFF + k] = __float2half(W1[i]);
}

// ---------------- CSR build ----------------
__global__ void deg_kernel(const int* __restrict__ dst) {
    int i = blockIdx.x * blockDim.x + threadIdx.x;
    if (i >= PP * EE) return;
    int p = i / EE;
    atomicAdd(&g_deg[p * NN + dst[i]], 1);
}

// phase 1: per-chunk sums
__global__ void bsum_kernel() {
    __shared__ int sred[256];
    int b = blockIdx.x;                 // p*NCH + c
    int p = b / NCH, c = b % NCH;
    int base = c * CH;
    int tid = threadIdx.x;
    int s = 0;
    #pragma unroll
    for (int j = 0; j < CH; j += 256) {
        int i = base + j + tid;
        if (i < NN) s += g_deg[p * NN + i];
    }
    sred[tid] = s;
    __syncthreads();
    for (int d = 128; d > 0; d >>= 1) {
        if (tid < d) sred[tid] += sred[tid + d];
        __syncthreads();
    }
    if (tid == 0) g_bsum[b] = sred[0];
}

// phase 2: scan chunk sums (tiny)
__global__ void bscan_kernel() {
    int p = threadIdx.x;
    if (p < PP) {
        int run = 0;
        for (int c = 0; c < NCH; c++) {
            g_boff[p * NCH + c] = run;
            run += g_bsum[p * NCH + c];
        }
    }
}

// phase 3: per-chunk block scan + add chunk offset
__global__ void cscan_kernel() {
    __shared__ int wsums[32];
    int b = blockIdx.x;
    int p = b / NCH, c = b % NCH;
    int tid = threadIdx.x, lane = tid & 31, wid = tid >> 5;
    int i = c * CH + tid;
    int v = (i < NN) ? g_deg[p * NN + i] : 0;
    int x = v;
    #pragma unroll
    for (int d = 1; d < 32; d <<= 1) {
        int t2 = __shfl_up_sync(0xffffffffu, x, d);
        if (lane >= d) x += t2;
    }
    if (lane == 31) wsums[wid] = x;
    __syncthreads();
    if (wid == 0) {
        int y = wsums[lane];
        #pragma unroll
        for (int d = 1; d < 32; d <<= 1) {
            int t2 = __shfl_up_sync(0xffffffffu, y, d);
            if (lane >= d) y += t2;
        }
        wsums[lane] = y;
    }
    __syncthreads();
    int incl = x + (wid ? wsums[wid - 1] : 0) + g_boff[b];
    if (i < NN) {
        g_off[p * (NN + 1) + i + 1] = incl;
        g_cur[p * NN + i] = incl - v;
    }
    if (tid == 0 && c == 0) g_off[p * (NN + 1)] = 0;
}

__global__ void fill_kernel(const int* __restrict__ src, const int* __restrict__ dst) {
    int i = blockIdx.x * blockDim.x + threadIdx.x;
    if (i >= PP * EE) return;
    int p = i / EE;
    int d = dst[i];
    int slot = atomicAdd(&g_cur[p * NN + d], 1);
    g_csr[p * EE + slot] = src[i];
}

// ---------------- projection GEMM + fused el/er epilogue (tf32) ----------------
__global__ __launch_bounds__(256, 2) void gemm_proj_tc(const float* __restrict__ A,
                                                       const float* __restrict__ Wg,
                                                       const float* __restrict__ al,
                                                       const float* __restrict__ ar) {
    int p = blockIdx.z;
    const float* B = Wg + (size_t)p * IND * HFF;
    __half* C = g_hp16 + (size_t)p * NN * HFF;

    __shared__ uint32_t As[128][20];
    __shared__ uint32_t Bs[16][136];

    int tid = threadIdx.x;
    int warp = tid >> 5, lane = tid & 31;
    int group = lane >> 2, tid4 = lane & 3;
    int warp_m = (warp >> 2) * 64, warp_n = (warp & 3) * 32;
    int m0 = blockIdx.x * 128, n0 = blockIdx.y * 128;

    int mA = tid >> 2, kA = (tid & 3) << 2;
    int kB = tid >> 5, nB = (tid & 31) << 2;

    float acc[4][4][4] = {};

    int rowA0 = m0 + mA;       if (rowA0 >= NN) rowA0 = NN - 1;
    int rowA1 = m0 + mA + 64;  if (rowA1 >= NN) rowA1 = NN - 1;

    for (int k0 = 0; k0 < IND; k0 += 16) {
        float4 a0 = *(const float4*)(A + (size_t)rowA0 * IND + k0 + kA);
        float4 a1 = *(const float4*)(A + (size_t)rowA1 * IND + k0 + kA);
        float4 b0 = *(const float4*)(B + (size_t)(k0 + kB) * HFF + n0 + nB);
        float4 b1 = *(const float4*)(B + (size_t)(k0 + kB + 8) * HFF + n0 + nB);
        __syncthreads();
        {
            uint4 u0 = {f2tf32(a0.x), f2tf32(a0.y), f2tf32(a0.z), f2tf32(a0.w)};
            uint4 u1 = {f2tf32(a1.x), f2tf32(a1.y), f2tf32(a1.z), f2tf32(a1.w)};
            *(uint4*)&As[mA][kA] = u0;
            *(uint4*)&As[mA + 64][kA] = u1;
            uint4 v0 = {f2tf32(b0.x), f2tf32(b0.y), f2tf32(b0.z), f2tf32(b0.w)};
            uint4 v1 = {f2tf32(b1.x), f2tf32(b1.y), f2tf32(b1.z), f2tf32(b1.w)};
            *(uint4*)&Bs[kB][nB] = v0;
            *(uint4*)&Bs[kB + 8][nB] = v1;
        }
        __syncthreads();
        #pragma unroll
        for (int kk = 0; kk < 16; kk += 8) {
            uint32_t af[4][4], bf[4][2];
            #pragma unroll
            for (int mi = 0; mi < 4; mi++) {
                int r0 = warp_m + mi * 16 + group;
                af[mi][0] = As[r0][kk + tid4];
                af[mi][1] = As[r0 + 8][kk + tid4];
                af[mi][2] = As[r0][kk + tid4 + 4];
                af[mi][3] = As[r0 + 8][kk + tid4 + 4];
            }
            #pragma unroll
            for (int ni = 0; ni < 4; ni++) {
                int cc = warp_n + ni * 8 + group;
                bf[ni][0] = Bs[kk + tid4][cc];
                bf[ni][1] = Bs[kk + tid4 + 4][cc];
            }
            #pragma unroll
            for (int mi = 0; mi < 4; mi++)
                #pragma unroll
                for (int ni = 0; ni < 4; ni++)
                    mma_tf32(acc[mi][ni], af[mi], bf[ni]);
        }
    }

    #pragma unroll
    for (int mi = 0; mi < 4; mi++) {
        int r_lo = m0 + warp_m + mi * 16 + group;
        #pragma unroll
        for (int ni = 0; ni < 4; ni++) {
            int col = n0 + warp_n + ni * 8 + (tid4 << 1);
            if (r_lo < NN) {
                __half2 o = __floats2half2_rn(acc[mi][ni][0], acc[mi][ni][1]);
                *(__half2*)(C + (size_t)r_lo * HFF + col) = o;
            }
            if (r_lo + 8 < NN) {
                __half2 o = __floats2half2_rn(acc[mi][ni][2], acc[mi][ni][3]);
                *(__half2*)(C + (size_t)(r_lo + 8) * HFF + col) = o;
            }
        }
    }

    int head = blockIdx.y * 4 + (warp_n >> 5);
    const float* alh = al + p * HFF + head * FF;
    const float* arh = ar + p * HFF + head * FF;
    #pragma unroll
    for (int mi = 0; mi < 4; mi++) {
        float el_lo = 0.f, el_hi = 0.f, er_lo = 0.f, er_hi = 0.f;
        #pragma unroll
        for (int ni = 0; ni < 4; ni++) {
            int f = ni * 8 + (tid4 << 1);
            float a0 = alh[f], a1 = alh[f + 1];
            float r0 = arh[f], r1 = arh[f + 1];
            el_lo += acc[mi][ni][0] * a0 + acc[mi][ni][1] * a1;
            er_lo += acc[mi][ni][0] * r0 + acc[mi][ni][1] * r1;
            el_hi += acc[mi][ni][2] * a0 + acc[mi][ni][3] * a1;
            er_hi += acc[mi][ni][2] * r0 + acc[mi][ni][3] * r1;
        }
        #pragma unroll
        for (int d = 1; d < 4; d <<= 1) {
            el_lo += __shfl_xor_sync(0xffffffffu, el_lo, d);
            er_lo += __shfl_xor_sync(0xffffffffu, er_lo, d);
            el_hi += __shfl_xor_sync(0xffffffffu, el_hi, d);
            er_hi += __shfl_xor_sync(0xffffffffu, er_hi, d);
        }
        if (tid4 == 0) {
            int r = m0 + warp_m + mi * 16 + group;
            if (r < NN) {
                g_el[((size_t)p * NN + r) * HH + head] = el_lo;
                g_er[((size_t)p * NN + r) * HH + head] = er_lo;
            }
            if (r + 8 < NN) {
                g_el[((size_t)p * NN + r + 8) * HH + head] = el_hi;
                g_er[((size_t)p * NN + r + 8) * HH + head] = er_hi;
            }
        }
    }
}

// ---------------- GAT edge softmax + aggregation (unroll x2) ----------------
__global__ __launch_bounds__(256) void attn_kernel(const float* __restrict__ bias) {
    int lane = threadIdx.x & 31;
    int v = blockIdx.x * 8 + (threadIdx.x >> 5);
    if (v >= NN) return;
    int p = blockIdx.y;
    int beg = g_off[p * (NN + 1) + v];
    int end = g_off[p * (NN + 1) + v + 1];
    const float*  __restrict__ elp = g_el + (size_t)p * NN * HH;
    const __half* __restrict__ hpp = g_hp16 + (size_t)p * NN * HFF;
    const int*    __restrict__ csr = g_csr + (size_t)p * EE;
    float er_l = 0.f;
    if (lane < HH) er_l = g_er[((size_t)p * NN + v) * HH + lane];
    int h = lane >> 2;
    float den = 0.f;
    float acc[8] = {};
    int i = beg;
    for (; i + 1 < end; i += 2) {
        int s0 = csr[i], s1 = csr[i + 1];
        float a0v = 0.f, a1v = 0.f;
        if (lane < HH) {
            float e0 = elp[(size_t)s0 * HH + lane] + er_l;
            float e1 = elp[(size_t)s1 * HH + lane] + er_l;
            e0 = e0 > 0.f ? e0 : 0.2f * e0;
            e1 = e1 > 0.f ? e1 : 0.2f * e1;
            a0v = __expf(e0);
            a1v = __expf(e1);
            den += a0v + a1v;
        }
        float ah0 = __shfl_sync(0xffffffffu, a0v, h);
        float ah1 = __shfl_sync(0xffffffffu, a1v, h);
        uint4 r0 = *(const uint4*)(hpp + (size_t)s0 * HFF + (lane << 3));
        uint4 r1 = *(const uint4*)(hpp + (size_t)s1 * HFF + (lane << 3));
        float2 p0 = __half22float2(*(__half2*)&r0.x);
        float2 p1 = __half22float2(*(__half2*)&r0.y);
        float2 p2 = __half22float2(*(__half2*)&r0.z);
        float2 p3 = __half22float2(*(__half2*)&r0.w);
        acc[0] += ah0 * p0.x; acc[1] += ah0 * p0.y;
        acc[2] += ah0 * p1.x; acc[3] += ah0 * p1.y;
        acc[4] += ah0 * p2.x; acc[5] += ah0 * p2.y;
        acc[6] += ah0 * p3.x; acc[7] += ah0 * p3.y;
        float2 q0 = __half22float2(*(__half2*)&r1.x);
        float2 q1 = __half22float2(*(__half2*)&r1.y);
        float2 q2 = __half22float2(*(__half2*)&r1.z);
        float2 q3 = __half22float2(*(__half2*)&r1.w);
        acc[0] += ah1 * q0.x; acc[1] += ah1 * q0.y;
        acc[2] += ah1 * q1.x; acc[3] += ah1 * q1.y;
        acc[4] += ah1 * q2.x; acc[5] += ah1 * q2.y;
        acc[6] += ah1 * q3.x; acc[7] += ah1 * q3.y;
    }
    if (i < end) {
        int s = csr[i];
        float a = 0.f;
        if (lane < HH) {
            float e = elp[(size_t)s * HH + lane] + er_l;
            e = e > 0.f ? e : 0.2f * e;
            a = __expf(e);
            den += a;
        }
        float ah = __shfl_sync(0xffffffffu, a, h);
        uint4 raw = *(const uint4*)(hpp + (size_t)s * HFF + (lane << 3));
        float2 f0 = __half22float2(*(__half2*)&raw.x);
        float2 f1 = __half22float2(*(__half2*)&raw.y);
        float2 f2 = __half22float2(*(__half2*)&raw.z);
        float2 f3 = __half22float2(*(__half2*)&raw.w);
        acc[0] += ah * f0.x; acc[1] += ah * f0.y;
        acc[2] += ah * f1.x; acc[3] += ah * f1.y;
        acc[4] += ah * f2.x; acc[5] += ah * f2.y;
        acc[6] += ah * f3.x; acc[7] += ah * f3.y;
    }
    float dh = __shfl_sync(0xffffffffu, den, h);
    float inv = (end > beg) ? 1.f / dh : 0.f;
    const float* bp = bias + p * HFF + (lane << 3);
    float4 b0 = *(const float4*)(bp);
    float4 b1 = *(const float4*)(bp + 4);
    float o0 = eluf(acc[0] * inv + b0.x);
    float o1 = eluf(acc[1] * inv + b0.y);
    float o2 = eluf(acc[2] * inv + b0.z);
    float o3 = eluf(acc[3] * inv + b0.w);
    float o4 = eluf(acc[4] * inv + b1.x);
    float o5 = eluf(acc[5] * inv + b1.y);
    float o6 = eluf(acc[6] * inv + b1.z);
    float o7 = eluf(acc[7] * inv + b1.w);
    uint4 out;
    *(__half2*)&out.x = __floats2half2_rn(o0, o1);
    *(__half2*)&out.y = __floats2half2_rn(o2, o3);
    *(__half2*)&out.z = __floats2half2_rn(o4, o5);
    *(__half2*)&out.w = __floats2half2_rn(o6, o7);
    *(uint4*)(g_z16 + ((size_t)p * NN + v) * HFF + (lane << 3)) = out;
}

// ---------------- semantic attention GEMM (fp16 HMMA) ----------
// A = g_z16 [MSEM][256] fp16, B = g_W1h [128 n][256 k] fp16. BM=128 BN=128=HSS.
__global__ __launch_bounds__(256, 2) void gemm_sem_f16(const float* __restrict__ b1,
                                                       const float* __restrict__ W2) {
    __shared__ uint32_t As[128][12];   // [m][k-pair], stride 12 -> conflict-free frags
    __shared__ uint32_t Bs[128][12];   // [n][k-pair]
    __shared__ float spsum[PP];

    int tid = threadIdx.x;
    int warp = tid >> 5, lane = tid & 31;
    int group = lane >> 2, tid4 = lane & 3;
    int warp_m = (warp >> 2) * 64, warp_n = (warp & 3) * 32;
    int m0 = blockIdx.x * 128;

    if (tid < PP) spsum[tid] = 0.f;

    int mA = tid >> 1, kHalf = (tid & 1) << 3;   // 8 halfs per thread

    float acc[4][4][4] = {};

    int rowA = m0 + mA;  if (rowA >= MSEM) rowA = MSEM - 1;

    for (int k0 = 0; k0 < HFF; k0 += 16) {
        uint4 av = *(const uint4*)(g_z16 + (size_t)rowA * HFF + k0 + kHalf);
        uint4 bv = *(const uint4*)(g_W1h + (size_t)mA * HFF + k0 + kHalf);
        __syncthreads();
        *(uint4*)&As[mA][(tid & 1) << 2] = av;
        *(uint4*)&Bs[mA][(tid & 1) << 2] = bv;
        __syncthreads();
        #pragma unroll
        for (int kk = 0; kk < 16; kk += 8) {
            int ki = (kk >> 1) + tid4;
            uint32_t af[4][2], bf[4];
            #pragma unroll
            for (int mi = 0; mi < 4; mi++) {
                int r0 = warp_m + mi * 16 + group;
                af[mi][0] = As[r0][ki];
                af[mi][1] = As[r0 + 8][ki];
            }
            #pragma unroll
            for (int ni = 0; ni < 4; ni++) {
                int cc = warp_n + ni * 8 + group;
                bf[ni] = Bs[cc][ki];
            }
            #pragma unroll
            for (int mi = 0; mi < 4; mi++)
                #pragma unroll
                for (int ni = 0; ni < 4; ni++)
                    mma_f16(acc[mi][ni], af[mi][0], af[mi][1], bf[ni]);
        }
    }

    #pragma unroll
    for (int mi = 0; mi < 4; mi++) {
        float s_lo = 0.f, s_hi = 0.f;
        #pragma unroll
        for (int ni = 0; ni < 4; ni++) {
            int col = warp_n + ni * 8 + (tid4 << 1);
            float bb0 = b1[col], bb1 = b1[col + 1];
            float w0 = W2[col], w1 = W2[col + 1];
            s_lo += tanhf(acc[mi][ni][0] + bb0) * w0 + tanhf(acc[mi][ni][1] + bb1) * w1;
            s_hi += tanhf(acc[mi][ni][2] + bb0) * w0 + tanhf(acc[mi][ni][3] + bb1) * w1;
        }
        #pragma unroll
        for (int d = 1; d < 4; d <<= 1) {
            s_lo += __shfl_xor_sync(0xffffffffu, s_lo, d);
            s_hi += __shfl_xor_sync(0xffffffffu, s_hi, d);
        }
        if (tid4 == 0) {
            int r = m0 + warp_m + mi * 16 + group;
            if (r < MSEM)     atomicAdd(&spsum[r / NN], s_lo);
            if (r + 8 < MSEM) atomicAdd(&spsum[(r + 8) / NN], s_hi);
        }
    }
    __syncthreads();
    if (tid < PP) atomicAdd(&g_wsum[tid], spsum[tid]);
}

// ---------------- beta softmax ----------------
__global__ void beta_kernel() {
    if (threadIdx.x == 0 && blockIdx.x == 0) {
        float w[PP], m = -1e30f, s = 0.f;
        #pragma unroll
        for (int p = 0; p < PP; p++) { w[p] = g_wsum[p] / (float)NN; m = fmaxf(m, w[p]); }
        #pragma unroll
        for (int p = 0; p < PP; p++) { w[p] = __expf(w[p] - m); s += w[p]; }
        #pragma unroll
        for (int p = 0; p < PP; p++) g_beta[p] = w[p] / s;
    }
}

// ---------------- fused embedding + per-graph pooling (smem-binned) ----------------
#define POOL_CHUNK 1024
__global__ __launch_bounds__(256) void pool_kernel(const int* __restrict__ gids) {
    __shared__ float bin[BB][64];
    int tid = threadIdx.x;
    int cy = blockIdx.y;
    int n0 = blockIdx.x * POOL_CHUNK;
    #pragma unroll
    for (int k = tid; k < BB * 64; k += 256) ((float*)bin)[k] = 0.f;
    __syncthreads();
    float bb0 = g_beta[0], bb1 = g_beta[1], bb2 = g_beta[2], bb3 = g_beta[3];
    int c = (tid & 15) << 2;
    int colg = cy * 64 + c;
    int nend = n0 + POOL_CHUNK; if (nend > NN) nend = NN;
    for (int n = n0 + (tid >> 4); n < nend; n += 16) {
        int g = gids[n];
        uint2 r0 = *(const uint2*)(g_z16 + ((size_t)0 * NN + n) * HFF + colg);
        uint2 r1 = *(const uint2*)(g_z16 + ((size_t)1 * NN + n) * HFF + colg);
        uint2 r2 = *(const uint2*)(g_z16 + ((size_t)2 * NN + n) * HFF + colg);
        uint2 r3 = *(const uint2*)(g_z16 + ((size_t)3 * NN + n) * HFF + colg);
        float2 a0 = __half22float2(*(__half2*)&r0.x), a1 = __half22float2(*(__half2*)&r0.y);
        float2 b0 = __half22float2(*(__half2*)&r1.x), b1 = __half22float2(*(__half2*)&r1.y);
        float2 c0 = __half22float2(*(__half2*)&r2.x), c1 = __half22float2(*(__half2*)&r2.y);
        float2 d0 = __half22float2(*(__half2*)&r3.x), d1 = __half22float2(*(__half2*)&r3.y);
        float f0 = bb0 * a0.x + bb1 * b0.x + bb2 * c0.x + bb3 * d0.x;
        float f1 = bb0 * a0.y + bb1 * b0.y + bb2 * c0.y + bb3 * d0.y;
        float f2 = bb0 * a1.x + bb1 * b1.x + bb2 * c1.x + bb3 * d1.x;
        float f3 = bb0 * a1.y + bb1 * b1.y + bb2 * c1.y + bb3 * d1.y;
        atomicAdd(&bin[g][c + 0], f0);
        atomicAdd(&bin[g][c + 1], f1);
        atomicAdd(&bin[g][c + 2], f2);
        atomicAdd(&bin[g][c + 3], f3);
    }
    __syncthreads();
    for (int k = tid; k < BB * 64; k += 256) {
        int g = k >> 6, cc = k & 63;
        float v = bin[g][cc];
        if (v != 0.f) atomicAdd(&g_pooled[g * HFF + cy * 64 + cc], v);
    }
}

// ---------------- pooled normalize + classifier ----------------
__global__ __launch_bounds__(256) void final_kernel(const float* __restrict__ clsW,
                                                    const float* __restrict__ clsb,
                                                    float* __restrict__ out) {
    int g = blockIdx.x;
    int t = threadIdx.x;
    float cnt = (float)g_cnt[g];
    float inv = 1.f / fmaxf(cnt, 1.f);
    float pv = g_pooled[g * HFF + t] * inv;
    out[BB * OUTC + g * HFF + t] = pv;
    __shared__ float s0[256], s1[256];
    s0[t] = pv * clsW[t * OUTC + 0];
    s1[t] = pv * clsW[t * OUTC + 1];
    __syncthreads();
    for (int d = 128; d > 0; d >>= 1) {
        if (t < d) { s0[t] += s0[t + d]; s1[t] += s1[t + d]; }
        __syncthreads();
    }
    if (t == 0) {
        out[g * OUTC + 0] = s0[0] + clsb[0];
        out[g * OUTC + 1] = s1[0] + clsb[1];
    }
}

// ---------------- launch ----------------
extern "C" void kernel_launch(void* const* d_in, const int* in_sizes, int n_in,
                              void* d_out, int out_size) {
    const float* h    = (const float*)d_in[0];
    const float* Wg   = (const float*)d_in[1];
    const float* al   = (const float*)d_in[2];
    const float* ar   = (const float*)d_in[3];
    const float* gb   = (const float*)d_in[4];
    const float* sW1  = (const float*)d_in[5];
    const float* sb1  = (const float*)d_in[6];
    const float* sW2  = (const float*)d_in[7];
    const float* cW   = (const float*)d_in[8];
    const float* cb   = (const float*)d_in[9];
    const int*   src  = (const int*)d_in[10];
    const int*   dst  = (const int*)d_in[11];
    const int*   gid  = (const int*)d_in[12];
    float* out = (float*)d_out;

    zero_kernel<<<(PP * NN + 255) / 256, 256>>>(gid);
    w1h_kernel<<<(HFF * HSS + 255) / 256, 256>>>(sW1);
    deg_kernel<<<(PP * EE + 255) / 256, 256>>>(dst);
    bsum_kernel<<<PP * NCH, 256>>>();
    bscan_kernel<<<1, 32>>>();
    cscan_kernel<<<PP * NCH, CH>>>();
    fill_kernel<<<(PP * EE + 255) / 256, 256>>>(src, dst);

    dim3 gp((NN + 127) / 128, 2, PP);
    gemm_proj_tc<<<gp, 256>>>(h, Wg, al, ar);

    dim3 ga((NN + 7) / 8, PP);
    attn_kernel<<<ga, 256>>>(gb);

    dim3 gs((MSEM + 127) / 128, 1);
    gemm_sem_f16<<<gs, 256>>>(sb1, sW2);

    beta_kernel<<<1, 32>>>();
    dim3 gpool((NN + POOL_CHUNK - 1) / POOL_CHUNK, 4);
    pool_kernel<<<gpool, 256>>>(gid);
    final_kernel<<<BB, 256>>>(cW, cb, out);
}